// round 1
// baseline (speedup 1.0000x reference)
#include <cuda_runtime.h>
#include <math.h>

#define B_   4
#define S_   1024
#define H_   768
#define NH_  12
#define DH_  64
#define POS_ 2048

// ---------------- scratch (static device arrays; no allocations) ----------------
__device__ float g_qh [B_*S_*H_];     // (B,S,NH,DH) = hidden @ q
__device__ float g_kvh[B_*S_*H_];     // (B,S,NH,DH) = hidden @ kv
__device__ float g_kr [B_*POS_*H_];   // (B,POS,NH,DH) = pos_emb @ r
__device__ float g_rwb[B_*NH_*S_];    // dot(r_w_bias[n], kvh[b,j,n,:])
__device__ float g_rrb[B_*NH_*POS_];  // dot(r_r_bias[n], kr[b,p,n,:])
__device__ float g_ctx[B_*S_*H_];     // attention output (B,S,NH,DH)

// ---------------- 64x64 tile SGEMM, row-major, C = A @ B -----------------------
// M,N multiples of 64, K multiple of 16. 256 threads, 4x4 microtile.
__global__ __launch_bounds__(256) void sgemm64(
    const float* __restrict__ A, const float* __restrict__ Bm,
    float* __restrict__ C, int M, int N, int K)
{
    __shared__ float AsT[16][64];
    __shared__ float Bs [16][64];
    const int tid = threadIdx.x;
    const int tx = tid & 15, ty = tid >> 4;
    const int r0 = ty * 4, c0 = tx * 4;
    const int row0 = blockIdx.y * 64, col0 = blockIdx.x * 64;
    const int lr = tid >> 2, lk = (tid & 3) * 4;   // A-tile load coords
    const int bk = tid >> 4, bc = (tid & 15) * 4;  // B-tile load coords
    float acc[4][4];
#pragma unroll
    for (int i = 0; i < 4; i++)
#pragma unroll
        for (int j = 0; j < 4; j++) acc[i][j] = 0.f;

    for (int k0 = 0; k0 < K; k0 += 16) {
        float4 a = *(const float4*)&A[(size_t)(row0 + lr) * K + k0 + lk];
        AsT[lk+0][lr] = a.x; AsT[lk+1][lr] = a.y;
        AsT[lk+2][lr] = a.z; AsT[lk+3][lr] = a.w;
        *(float4*)&Bs[bk][bc] = *(const float4*)&Bm[(size_t)(k0 + bk) * N + col0 + bc];
        __syncthreads();
#pragma unroll
        for (int kk = 0; kk < 16; ++kk) {
            float4 av = *(float4*)&AsT[kk][r0];
            float4 bv = *(float4*)&Bs[kk][c0];
            float aa[4] = {av.x, av.y, av.z, av.w};
            float bb[4] = {bv.x, bv.y, bv.z, bv.w};
#pragma unroll
            for (int i = 0; i < 4; i++)
#pragma unroll
                for (int j = 0; j < 4; j++) acc[i][j] += aa[i] * bb[j];
        }
        __syncthreads();
    }
#pragma unroll
    for (int i = 0; i < 4; i++) {
        float4 v = make_float4(acc[i][0], acc[i][1], acc[i][2], acc[i][3]);
        *(float4*)&C[(size_t)(row0 + r0 + i) * N + col0 + c0] = v;
    }
}

// ---------- output GEMM with bias + residual + exact GELU epilogue -------------
__global__ __launch_bounds__(256) void sgemm_out(
    const float* __restrict__ A, const float* __restrict__ Bm,
    const float* __restrict__ bias, const float* __restrict__ resid,
    float* __restrict__ C, int M, int N, int K)
{
    __shared__ float AsT[16][64];
    __shared__ float Bs [16][64];
    const int tid = threadIdx.x;
    const int tx = tid & 15, ty = tid >> 4;
    const int r0 = ty * 4, c0 = tx * 4;
    const int row0 = blockIdx.y * 64, col0 = blockIdx.x * 64;
    const int lr = tid >> 2, lk = (tid & 3) * 4;
    const int bk = tid >> 4, bc = (tid & 15) * 4;
    float acc[4][4];
#pragma unroll
    for (int i = 0; i < 4; i++)
#pragma unroll
        for (int j = 0; j < 4; j++) acc[i][j] = 0.f;

    for (int k0 = 0; k0 < K; k0 += 16) {
        float4 a = *(const float4*)&A[(size_t)(row0 + lr) * K + k0 + lk];
        AsT[lk+0][lr] = a.x; AsT[lk+1][lr] = a.y;
        AsT[lk+2][lr] = a.z; AsT[lk+3][lr] = a.w;
        *(float4*)&Bs[bk][bc] = *(const float4*)&Bm[(size_t)(k0 + bk) * N + col0 + bc];
        __syncthreads();
#pragma unroll
        for (int kk = 0; kk < 16; ++kk) {
            float4 av = *(float4*)&AsT[kk][r0];
            float4 bv = *(float4*)&Bs[kk][c0];
            float aa[4] = {av.x, av.y, av.z, av.w};
            float bb[4] = {bv.x, bv.y, bv.z, bv.w};
#pragma unroll
            for (int i = 0; i < 4; i++)
#pragma unroll
                for (int j = 0; j < 4; j++) acc[i][j] += aa[i] * bb[j];
        }
        __syncthreads();
    }
#pragma unroll
    for (int i = 0; i < 4; i++) {
        const int row = row0 + r0 + i;
#pragma unroll
        for (int j = 0; j < 4; j++) {
            const int col = col0 + c0 + j;
            float x = acc[i][j] + bias[col] + resid[(size_t)row * N + col];
            float g = 0.5f * x * (1.f + erff(x * 0.70710678118654752f));
            C[(size_t)row * N + col] = g;
        }
    }
}

// ---- per-(b,pos,head) bias dots: out[(b*NH+n)*L + j] = dot(w[n,:], X[b,j,n,:]) ----
__global__ void bias_dot(const float* __restrict__ X, const float* __restrict__ w,
                         float* __restrict__ out, int L)
{
    const int g = blockIdx.x * (blockDim.x >> 5) + (threadIdx.x >> 5);
    const int lane = threadIdx.x & 31;
    if (g >= B_ * L * NH_) return;
    const int n = g % NH_;
    const int j = (g / NH_) % L;
    const int b = g / (NH_ * L);
    const float* x  = X + ((size_t)((size_t)b * L + j) * NH_ + n) * DH_;
    const float* ww = w + n * DH_;
    float v = x[lane] * ww[lane] + x[lane + 32] * ww[lane + 32];
#pragma unroll
    for (int off = 16; off; off >>= 1) v += __shfl_xor_sync(0xffffffffu, v, off);
    if (!lane) out[((size_t)b * NH_ + n) * L + j] = v;
}

// ---------------- fused flash attention with folded rel_shift -------------------
// Per block: (b, n, 64 query rows). Online softmax over 16 key tiles of 64.
// bd_shifted[i,j] = dot(q[i], kr[1024 + j - i]); per 64x64 tile the needed kr
// rows form a 127-row window [pbase, pbase+126], always within [1,2047].
__global__ __launch_bounds__(256) void flash_attn(const float* __restrict__ mask)
{
    extern __shared__ float sm[];
    float* q_s  = sm;               // 64 x 65
    float* kv_s = sm + 64 * 65;     // 64 x 65
    float* p_s  = sm + 2 * 64 * 65; // 64 x 65
    float* kr_s = sm + 3 * 64 * 65; // 127 x 65
    const int b = blockIdx.z, n = blockIdx.y;
    const int i0 = blockIdx.x * 64;
    const int tid = threadIdx.x, tx = tid & 15, ty = tid >> 4;
    const int r0 = ty * 4, c0 = tx * 4;

    // load Q tile
    for (int v = tid; v < 64 * 16; v += 256) {
        int r = v >> 4, fq = (v & 15) * 4;
        float4 t = *(const float4*)&g_qh[(((size_t)b * S_ + i0 + r) * NH_ + n) * DH_ + fq];
        float* d = &q_s[r * 65 + fq];
        d[0] = t.x; d[1] = t.y; d[2] = t.z; d[3] = t.w;
    }

    float m[4], l[4], o[4][4];
#pragma unroll
    for (int i = 0; i < 4; i++) {
        m[i] = -1e30f; l[i] = 0.f;
#pragma unroll
        for (int j = 0; j < 4; j++) o[i][j] = 0.f;
    }
    const float* rwb_bn = g_rwb + ((size_t)b * NH_ + n) * S_;
    const float* rrb_bn = g_rrb + ((size_t)b * NH_ + n) * POS_;

    for (int jt = 0; jt < 16; ++jt) {
        const int j0 = jt * 64;
        const int pbase = 1024 + j0 - i0 - 63;
        __syncthreads();  // previous P@V done before overwriting kv_s/kr_s
        for (int v = tid; v < 64 * 16; v += 256) {
            int r = v >> 4, fq = (v & 15) * 4;
            float4 t = *(const float4*)&g_kvh[(((size_t)b * S_ + j0 + r) * NH_ + n) * DH_ + fq];
            float* d = &kv_s[r * 65 + fq];
            d[0] = t.x; d[1] = t.y; d[2] = t.z; d[3] = t.w;
        }
        for (int v = tid; v < 127 * 16; v += 256) {
            int r = v >> 4, fq = (v & 15) * 4;
            float4 t = *(const float4*)&g_kr[(((size_t)b * POS_ + pbase + r) * NH_ + n) * DH_ + fq];
            float* d = &kr_s[r * 65 + fq];
            d[0] = t.x; d[1] = t.y; d[2] = t.z; d[3] = t.w;
        }
        __syncthreads();

        float s[4][4];
#pragma unroll
        for (int i = 0; i < 4; i++)
#pragma unroll
            for (int j = 0; j < 4; j++) s[i][j] = 0.f;

        const int dbase = c0 - r0 + 60;  // kr_s row for (rr=3, cc=0) diagonal
#pragma unroll 4
        for (int d = 0; d < 64; ++d) {
            float qv[4], kvv[4], krv[7];
#pragma unroll
            for (int i = 0; i < 4; i++) qv[i] = q_s[(r0 + i) * 65 + d];
#pragma unroll
            for (int j = 0; j < 4; j++) kvv[j] = kv_s[(c0 + j) * 65 + d];
#pragma unroll
            for (int t = 0; t < 7; t++) krv[t] = kr_s[(dbase + t) * 65 + d];
#pragma unroll
            for (int i = 0; i < 4; i++)
#pragma unroll
                for (int j = 0; j < 4; j++)
                    s[i][j] += qv[i] * (kvv[j] + krv[j - i + 3]);
        }

        // scores -> masked, scaled; online softmax update
#pragma unroll
        for (int i = 0; i < 4; i++) {
            const int gi = i0 + r0 + i;
            const float* mrow = mask + ((size_t)b * S_ + gi) * S_ + j0;
            float rowmax = -1e30f;
#pragma unroll
            for (int j = 0; j < 4; j++) {
                const int gj = j0 + c0 + j;
                const int p = 1024 + gj - gi;
                float v = (s[i][j] + rwb_bn[gj] + rrb_bn[p]) * 0.125f
                          + mrow[c0 + j] * (-65500.0f);
                s[i][j] = v;
                rowmax = fmaxf(rowmax, v);
            }
#pragma unroll
            for (int off = 8; off; off >>= 1)
                rowmax = fmaxf(rowmax, __shfl_xor_sync(0xffffffffu, rowmax, off));
            const float mn = fmaxf(m[i], rowmax);
            const float corr = __expf(m[i] - mn);
            float lsum = 0.f;
#pragma unroll
            for (int j = 0; j < 4; j++) {
                float pv = __expf(s[i][j] - mn);
                s[i][j] = pv;
                lsum += pv;
            }
#pragma unroll
            for (int off = 8; off; off >>= 1)
                lsum += __shfl_xor_sync(0xffffffffu, lsum, off);
            l[i] = l[i] * corr + lsum;
            m[i] = mn;
#pragma unroll
            for (int j = 0; j < 4; j++) o[i][j] *= corr;
#pragma unroll
            for (int j = 0; j < 4; j++) p_s[(r0 + i) * 65 + c0 + j] = s[i][j];
        }
        __syncthreads();

        // O += P @ V (V = kvh tile)
#pragma unroll 2
        for (int c = 0; c < 64; ++c) {
            float pv[4], kvv[4];
#pragma unroll
            for (int i = 0; i < 4; i++) pv[i] = p_s[(r0 + i) * 65 + c];
#pragma unroll
            for (int j = 0; j < 4; j++) kvv[j] = kv_s[c * 65 + c0 + j];
#pragma unroll
            for (int i = 0; i < 4; i++)
#pragma unroll
                for (int j = 0; j < 4; j++) o[i][j] += pv[i] * kvv[j];
        }
    }

#pragma unroll
    for (int i = 0; i < 4; i++) {
        const float inv = 1.f / l[i];
#pragma unroll
        for (int j = 0; j < 4; j++)
            g_ctx[(((size_t)b * S_ + i0 + r0 + i) * NH_ + n) * DH_ + c0 + j] = o[i][j] * inv;
    }
}

// -------------------------------- launch ---------------------------------------
extern "C" void kernel_launch(void* const* d_in, const int* in_sizes, int n_in,
                              void* d_out, int out_size)
{
    const float* hidden   = (const float*)d_in[0];
    const float* pos_emb  = (const float*)d_in[1];
    const float* mask     = (const float*)d_in[2];
    const float* qw       = (const float*)d_in[3];
    const float* kvw      = (const float*)d_in[4];
    const float* rw       = (const float*)d_in[5];
    const float* r_r_bias = (const float*)d_in[6];
    const float* r_w_bias = (const float*)d_in[7];
    const float* w_out    = (const float*)d_in[8];
    const float* b_out    = (const float*)d_in[9];
    float* out = (float*)d_out;

    float *qh, *kvh, *kr, *rwb, *rrb, *ctx;
    cudaGetSymbolAddress((void**)&qh,  g_qh);
    cudaGetSymbolAddress((void**)&kvh, g_kvh);
    cudaGetSymbolAddress((void**)&kr,  g_kr);
    cudaGetSymbolAddress((void**)&rwb, g_rwb);
    cudaGetSymbolAddress((void**)&rrb, g_rrb);
    cudaGetSymbolAddress((void**)&ctx, g_ctx);

    const int smem = (3 * 64 * 65 + 127 * 65) * (int)sizeof(float);  // ~83 KB
    cudaFuncSetAttribute(flash_attn, cudaFuncAttributeMaxDynamicSharedMemorySize, smem);

    // projections
    sgemm64<<<dim3(12,  64), 256>>>(hidden,  qw,  qh,  B_*S_,   H_, H_);
    sgemm64<<<dim3(12,  64), 256>>>(hidden,  kvw, kvh, B_*S_,   H_, H_);
    sgemm64<<<dim3(12, 128), 256>>>(pos_emb, rw,  kr,  B_*POS_, H_, H_);

    // bias dot vectors
    bias_dot<<<(B_*S_*NH_*32 + 255) / 256, 256>>>(kvh, r_w_bias, rwb, S_);
    bias_dot<<<(B_*POS_*NH_*32 + 255) / 256, 256>>>(kr, r_r_bias, rrb, POS_);

    // fused attention (ac + shifted bd + mask + softmax + alpha@V)
    flash_attn<<<dim3(S_/64, NH_, B_), 256, smem>>>(mask);

    // output projection + bias + residual + exact GELU
    sgemm_out<<<dim3(12, 64), 256>>>(ctx, w_out, b_out, hidden, out, B_*S_, H_, H_);
}

// round 2
// speedup vs baseline: 1.5540x; 1.5540x over previous
#include <cuda_runtime.h>
#include <math.h>
#include <stdint.h>

#define B_   4
#define S_   1024
#define H_   768
#define NH_  12
#define DH_  64
#define POS_ 2048

// ---------------- scratch (static device arrays; no allocations) ----------------
__device__ float g_qh [B_*S_*H_];     // (B,S,NH,DH) = hidden @ q
__device__ float g_kvh[B_*S_*H_];     // (B,S,NH,DH) = hidden @ kv
__device__ float g_kr [B_*POS_*H_];   // (B,POS,NH,DH) = pos_emb @ r
__device__ float g_rwb[B_*NH_*S_];    // dot(r_w_bias[n], kvh[b,j,n,:])
__device__ float g_rrb[B_*NH_*POS_];  // dot(r_r_bias[n], kr[b,p,n,:])
__device__ float g_ctx[B_*S_*H_];     // attention output (B,S,NH,DH)

__device__ __forceinline__ uint32_t f2tf(float f) {
    uint32_t u;
    asm("cvt.rna.tf32.f32 %0, %1;" : "=r"(u) : "f"(f));
    return u;
}

__device__ __forceinline__ void mma8(float* d, const uint32_t* a, const uint32_t* b) {
    asm volatile(
        "mma.sync.aligned.m16n8k8.row.col.f32.tf32.tf32.f32 "
        "{%0,%1,%2,%3}, {%4,%5,%6,%7}, {%8,%9}, {%0,%1,%2,%3};"
        : "+f"(d[0]), "+f"(d[1]), "+f"(d[2]), "+f"(d[3])
        : "r"(a[0]), "r"(a[1]), "r"(a[2]), "r"(a[3]), "r"(b[0]), "r"(b[1]));
}

// ---------------- tf32 MMA GEMM: C = A(MxK) @ B(KxN), row-major --------------
// Block tile 128(M) x 64(N) x 32(K), 256 threads, warp grid 4(m) x 2(n),
// warp tile 32x32. M%128==0, N%64==0, K%32==0.
#define LDA_ 133
#define LDB_ 69
template<bool EPI>
__global__ __launch_bounds__(256) void gemm_tf32(
    const float* __restrict__ A, const float* __restrict__ Bm,
    float* __restrict__ C, int M, int N, int K,
    const float* __restrict__ bias, const float* __restrict__ resid)
{
    __shared__ uint32_t As[32 * LDA_];   // [k][m]
    __shared__ uint32_t Bs[32 * LDB_];   // [k][n]
    const int tid = threadIdx.x;
    const int m0 = blockIdx.y * 128, n0 = blockIdx.x * 64;
    const int wid = tid >> 5, lane = tid & 31;
    const int wm = wid & 3, wn = wid >> 2;
    const int g = lane >> 2, tig = lane & 3;
    const int ar = tid >> 3, ac4 = (tid & 7) * 4;
    const int br = tid >> 4, bc4 = (tid & 15) * 4;

    float acc[2][4][4];
#pragma unroll
    for (int mi = 0; mi < 2; mi++)
#pragma unroll
        for (int ni = 0; ni < 4; ni++)
#pragma unroll
            for (int e = 0; e < 4; e++) acc[mi][ni][e] = 0.f;

    for (int k0 = 0; k0 < K; k0 += 32) {
#pragma unroll
        for (int rr = 0; rr < 4; rr++) {
            const int row = m0 + rr * 32 + ar;
            float4 v = *(const float4*)&A[(size_t)row * K + k0 + ac4];
            const int mm = rr * 32 + ar;
            As[(ac4 + 0) * LDA_ + mm] = f2tf(v.x);
            As[(ac4 + 1) * LDA_ + mm] = f2tf(v.y);
            As[(ac4 + 2) * LDA_ + mm] = f2tf(v.z);
            As[(ac4 + 3) * LDA_ + mm] = f2tf(v.w);
        }
#pragma unroll
        for (int pp = 0; pp < 2; pp++) {
            const int k = pp * 16 + br;
            float4 v = *(const float4*)&Bm[(size_t)(k0 + k) * N + n0 + bc4];
            Bs[k * LDB_ + bc4 + 0] = f2tf(v.x);
            Bs[k * LDB_ + bc4 + 1] = f2tf(v.y);
            Bs[k * LDB_ + bc4 + 2] = f2tf(v.z);
            Bs[k * LDB_ + bc4 + 3] = f2tf(v.w);
        }
        __syncthreads();
#pragma unroll
        for (int kc = 0; kc < 4; kc++) {
            const int kb = kc * 8;
            uint32_t afr[2][4];
#pragma unroll
            for (int mi = 0; mi < 2; mi++) {
                const int mr = wm * 32 + mi * 16;
                afr[mi][0] = As[(kb + tig) * LDA_ + mr + g];
                afr[mi][1] = As[(kb + tig) * LDA_ + mr + g + 8];
                afr[mi][2] = As[(kb + tig + 4) * LDA_ + mr + g];
                afr[mi][3] = As[(kb + tig + 4) * LDA_ + mr + g + 8];
            }
#pragma unroll
            for (int ni = 0; ni < 4; ni++) {
                const int nc = wn * 32 + ni * 8 + g;
                uint32_t bfr[2] = { Bs[(kb + tig) * LDB_ + nc],
                                    Bs[(kb + tig + 4) * LDB_ + nc] };
                mma8(acc[0][ni], afr[0], bfr);
                mma8(acc[1][ni], afr[1], bfr);
            }
        }
        __syncthreads();
    }
#pragma unroll
    for (int mi = 0; mi < 2; mi++) {
#pragma unroll
        for (int ni = 0; ni < 4; ni++) {
            const int row = m0 + wm * 32 + mi * 16 + g;
            const int col = n0 + wn * 32 + ni * 8 + 2 * tig;
#pragma unroll
            for (int half = 0; half < 2; half++) {
                const int r = row + half * 8;
#pragma unroll
                for (int e = 0; e < 2; e++) {
                    float v = acc[mi][ni][half * 2 + e];
                    const int c = col + e;
                    if (EPI) {
                        float x = v + bias[c] + resid[(size_t)r * N + c];
                        v = 0.5f * x * (1.f + erff(x * 0.70710678118654752f));
                    }
                    C[(size_t)r * N + c] = v;
                }
            }
        }
    }
}

// ---- per-(b,pos,head) bias dots: out[(b*NH+n)*L + j] = dot(w[n,:], X[b,j,n,:]) ----
__global__ void bias_dot(const float* __restrict__ X, const float* __restrict__ w,
                         float* __restrict__ out, int L)
{
    const int gidx = blockIdx.x * (blockDim.x >> 5) + (threadIdx.x >> 5);
    const int lane = threadIdx.x & 31;
    if (gidx >= B_ * L * NH_) return;
    const int n = gidx % NH_;
    const int j = (gidx / NH_) % L;
    const int b = gidx / (NH_ * L);
    const float* x  = X + ((size_t)((size_t)b * L + j) * NH_ + n) * DH_;
    const float* ww = w + n * DH_;
    float v = x[lane] * ww[lane] + x[lane + 32] * ww[lane + 32];
#pragma unroll
    for (int off = 16; off; off >>= 1) v += __shfl_xor_sync(0xffffffffu, v, off);
    if (!lane) out[((size_t)b * NH_ + n) * L + j] = v;
}

// ---------------- MMA flash attention with folded rel_shift --------------------
// Per block: (b, n, 64 query rows), 8 warps. Online softmax over 16 key tiles.
// S = Q@KV^T (MMA);  G[i,t] = Q@KR_window^T (MMA, 128 wide);  bd[i,j]=G[i,j-i+63].
#define LQ_ 69
#define LG_ 133
__global__ __launch_bounds__(256) void flash_mma(const float* __restrict__ mask)
{
    extern __shared__ uint32_t sm[];
    uint32_t* q_s  = sm;                  // 64 x LQ_, tf32
    uint32_t* kv_s = q_s  + 64 * LQ_;     // 64 x LQ_, tf32  ([j][d])
    uint32_t* kr_s = kv_s + 64 * LQ_;     // 128 x LQ_, tf32 ([t][d])
    uint32_t* s_s  = kr_s + 128 * LQ_;    // 64 x LQ_, f32 scores then tf32 P
    uint32_t* g_sm = s_s  + 64 * LQ_;     // 64 x LG_, f32 G
    float* m_s = (float*)(g_sm + 64 * LG_);
    float* l_s = m_s + 64;
    float* c_s = l_s + 64;

    const int b = blockIdx.z, n = blockIdx.y;
    const int i0 = blockIdx.x * 64;
    const int tid = threadIdx.x;
    const int wid = tid >> 5, lane = tid & 31;
    const int wm = wid & 3, wn = wid >> 2;
    const int g = lane >> 2, tig = lane & 3;

    // load Q tile (tf32)
    for (int idx = tid; idx < 64 * 16; idx += 256) {
        const int r = idx >> 4, c4 = (idx & 15) * 4;
        float4 v = *(const float4*)&g_qh[(((size_t)b * S_ + i0 + r) * NH_ + n) * DH_ + c4];
        q_s[r * LQ_ + c4 + 0] = f2tf(v.x);
        q_s[r * LQ_ + c4 + 1] = f2tf(v.y);
        q_s[r * LQ_ + c4 + 2] = f2tf(v.z);
        q_s[r * LQ_ + c4 + 3] = f2tf(v.w);
    }
    if (tid < 64) { m_s[tid] = -1e30f; l_s[tid] = 0.f; }
    for (int idx = tid; idx < LQ_; idx += 256) kr_s[127 * LQ_ + idx] = 0;  // pad row

    float acc_o[4][4];
#pragma unroll
    for (int ni = 0; ni < 4; ni++)
#pragma unroll
        for (int e = 0; e < 4; e++) acc_o[ni][e] = 0.f;

    const float* rwb_bn = g_rwb + ((size_t)b * NH_ + n) * S_;
    const float* rrb_bn = g_rrb + ((size_t)b * NH_ + n) * POS_;

    for (int jt = 0; jt < 16; ++jt) {
        const int j0 = jt * 64;
        const int pbase = 1024 + j0 - i0 - 63;
        __syncthreads();  // prior PV reads of kv_s/s_s complete
        for (int idx = tid; idx < 64 * 16; idx += 256) {
            const int r = idx >> 4, c4 = (idx & 15) * 4;
            float4 v = *(const float4*)&g_kvh[(((size_t)b * S_ + j0 + r) * NH_ + n) * DH_ + c4];
            kv_s[r * LQ_ + c4 + 0] = f2tf(v.x);
            kv_s[r * LQ_ + c4 + 1] = f2tf(v.y);
            kv_s[r * LQ_ + c4 + 2] = f2tf(v.z);
            kv_s[r * LQ_ + c4 + 3] = f2tf(v.w);
        }
        for (int idx = tid; idx < 127 * 16; idx += 256) {
            const int r = idx >> 4, c4 = (idx & 15) * 4;
            float4 v = *(const float4*)&g_kr[(((size_t)b * POS_ + pbase + r) * NH_ + n) * DH_ + c4];
            kr_s[r * LQ_ + c4 + 0] = f2tf(v.x);
            kr_s[r * LQ_ + c4 + 1] = f2tf(v.y);
            kr_s[r * LQ_ + c4 + 2] = f2tf(v.z);
            kr_s[r * LQ_ + c4 + 3] = f2tf(v.w);
        }
        __syncthreads();

        // ---- S (64x64) and G (64x128) via MMA ----
        float acc_s[4][4], acc_g[8][4];
#pragma unroll
        for (int ni = 0; ni < 4; ni++)
#pragma unroll
            for (int e = 0; e < 4; e++) acc_s[ni][e] = 0.f;
#pragma unroll
        for (int ni = 0; ni < 8; ni++)
#pragma unroll
            for (int e = 0; e < 4; e++) acc_g[ni][e] = 0.f;

        const int mr = wm * 16;
#pragma unroll
        for (int kc = 0; kc < 8; kc++) {
            const int kb = kc * 8;
            uint32_t af[4] = { q_s[(mr + g) * LQ_ + kb + tig],
                               q_s[(mr + g + 8) * LQ_ + kb + tig],
                               q_s[(mr + g) * LQ_ + kb + tig + 4],
                               q_s[(mr + g + 8) * LQ_ + kb + tig + 4] };
#pragma unroll
            for (int ni = 0; ni < 4; ni++) {
                const int nc = wn * 32 + ni * 8 + g;
                uint32_t bf[2] = { kv_s[nc * LQ_ + kb + tig],
                                   kv_s[nc * LQ_ + kb + tig + 4] };
                mma8(acc_s[ni], af, bf);
            }
#pragma unroll
            for (int ni = 0; ni < 8; ni++) {
                const int nc = wn * 64 + ni * 8 + g;
                uint32_t bf[2] = { kr_s[nc * LQ_ + kb + tig],
                                   kr_s[nc * LQ_ + kb + tig + 4] };
                mma8(acc_g[ni], af, bf);
            }
        }
        // store S, G to smem (f32 bits)
        {
            const int r0 = mr + g;
#pragma unroll
            for (int ni = 0; ni < 4; ni++) {
                const int c = wn * 32 + ni * 8 + 2 * tig;
                s_s[r0 * LQ_ + c]           = __float_as_uint(acc_s[ni][0]);
                s_s[r0 * LQ_ + c + 1]       = __float_as_uint(acc_s[ni][1]);
                s_s[(r0 + 8) * LQ_ + c]     = __float_as_uint(acc_s[ni][2]);
                s_s[(r0 + 8) * LQ_ + c + 1] = __float_as_uint(acc_s[ni][3]);
            }
#pragma unroll
            for (int ni = 0; ni < 8; ni++) {
                const int c = wn * 64 + ni * 8 + 2 * tig;
                g_sm[r0 * LG_ + c]           = __float_as_uint(acc_g[ni][0]);
                g_sm[r0 * LG_ + c + 1]       = __float_as_uint(acc_g[ni][1]);
                g_sm[(r0 + 8) * LG_ + c]     = __float_as_uint(acc_g[ni][2]);
                g_sm[(r0 + 8) * LG_ + c + 1] = __float_as_uint(acc_g[ni][3]);
            }
        }
        __syncthreads();

        // ---- softmax: 4 threads per row, 16 cols each ----
        {
            const int row = tid >> 2, qq = tid & 3;
            const int gi = i0 + row;
            const float mo = m_s[row], lo = l_s[row];
            const float* mrow = mask + ((size_t)b * S_ + gi) * S_ + j0 + qq * 16;
            float vbuf[16];
            float rmax = -1e30f;
#pragma unroll
            for (int c = 0; c < 16; c++) {
                const int col = qq * 16 + c;
                const float sv = __uint_as_float(s_s[row * LQ_ + col]);
                const float gv = __uint_as_float(g_sm[row * LG_ + col - row + 63]);
                const float v = (sv + gv + rwb_bn[j0 + col] + rrb_bn[1024 + j0 + col - gi]) * 0.125f
                                + mrow[c] * (-65500.0f);
                vbuf[c] = v;
                rmax = fmaxf(rmax, v);
            }
            rmax = fmaxf(rmax, __shfl_xor_sync(0xffffffffu, rmax, 1));
            rmax = fmaxf(rmax, __shfl_xor_sync(0xffffffffu, rmax, 2));
            const float mn = fmaxf(mo, rmax);
            const float corr = __expf(mo - mn);
            float ls = 0.f;
#pragma unroll
            for (int c = 0; c < 16; c++) {
                const float p = __expf(vbuf[c] - mn);
                ls += p;
                s_s[row * LQ_ + qq * 16 + c] = f2tf(p);
            }
            ls += __shfl_xor_sync(0xffffffffu, ls, 1);
            ls += __shfl_xor_sync(0xffffffffu, ls, 2);
            if (qq == 0) { m_s[row] = mn; l_s[row] = lo * corr + ls; c_s[row] = corr; }
        }
        __syncthreads();

        // ---- rescale O, then O += P @ V via MMA ----
        {
            const int mr2 = wm * 16;
            const float cr0 = c_s[mr2 + g], cr1 = c_s[mr2 + g + 8];
#pragma unroll
            for (int ni = 0; ni < 4; ni++) {
                acc_o[ni][0] *= cr0; acc_o[ni][1] *= cr0;
                acc_o[ni][2] *= cr1; acc_o[ni][3] *= cr1;
            }
        }
#pragma unroll
        for (int kc = 0; kc < 8; kc++) {
            const int kb = kc * 8;
            uint32_t af[4] = { s_s[(mr + g) * LQ_ + kb + tig],
                               s_s[(mr + g + 8) * LQ_ + kb + tig],
                               s_s[(mr + g) * LQ_ + kb + tig + 4],
                               s_s[(mr + g + 8) * LQ_ + kb + tig + 4] };
#pragma unroll
            for (int ni = 0; ni < 4; ni++) {
                const int dc = wn * 32 + ni * 8 + g;
                uint32_t bf[2] = { kv_s[(kb + tig) * LQ_ + dc],
                                   kv_s[(kb + tig + 4) * LQ_ + dc] };
                mma8(acc_o[ni], af, bf);
            }
        }
    }

    // ---- normalize and store ----
    {
        const int mr = wm * 16;
        const float inv0 = 1.f / l_s[mr + g];
        const float inv1 = 1.f / l_s[mr + g + 8];
        const size_t base0 = (((size_t)b * S_ + i0 + mr + g) * NH_ + n) * (size_t)DH_;
        const size_t base1 = (((size_t)b * S_ + i0 + mr + g + 8) * NH_ + n) * (size_t)DH_;
#pragma unroll
        for (int ni = 0; ni < 4; ni++) {
            const int col = wn * 32 + ni * 8 + 2 * tig;
            g_ctx[base0 + col]     = acc_o[ni][0] * inv0;
            g_ctx[base0 + col + 1] = acc_o[ni][1] * inv0;
            g_ctx[base1 + col]     = acc_o[ni][2] * inv1;
            g_ctx[base1 + col + 1] = acc_o[ni][3] * inv1;
        }
    }
}

// -------------------------------- launch ---------------------------------------
extern "C" void kernel_launch(void* const* d_in, const int* in_sizes, int n_in,
                              void* d_out, int out_size)
{
    const float* hidden   = (const float*)d_in[0];
    const float* pos_emb  = (const float*)d_in[1];
    const float* mask     = (const float*)d_in[2];
    const float* qw       = (const float*)d_in[3];
    const float* kvw      = (const float*)d_in[4];
    const float* rw       = (const float*)d_in[5];
    const float* r_r_bias = (const float*)d_in[6];
    const float* r_w_bias = (const float*)d_in[7];
    const float* w_out    = (const float*)d_in[8];
    const float* b_out    = (const float*)d_in[9];
    float* out = (float*)d_out;

    float *qh, *kvh, *kr, *rwb, *rrb, *ctx;
    cudaGetSymbolAddress((void**)&qh,  g_qh);
    cudaGetSymbolAddress((void**)&kvh, g_kvh);
    cudaGetSymbolAddress((void**)&kr,  g_kr);
    cudaGetSymbolAddress((void**)&rwb, g_rwb);
    cudaGetSymbolAddress((void**)&rrb, g_rrb);
    cudaGetSymbolAddress((void**)&ctx, g_ctx);

    const int smem = (64 * LQ_ * 3 + 128 * LQ_ + 64 * LG_ + 192) * (int)sizeof(uint32_t);
    cudaFuncSetAttribute(flash_mma, cudaFuncAttributeMaxDynamicSharedMemorySize, smem);

    // projections (tf32 MMA)
    gemm_tf32<false><<<dim3(12, 32), 256>>>(hidden,  qw,  qh,  B_*S_,   H_, H_, nullptr, nullptr);
    gemm_tf32<false><<<dim3(12, 32), 256>>>(hidden,  kvw, kvh, B_*S_,   H_, H_, nullptr, nullptr);
    gemm_tf32<false><<<dim3(12, 64), 256>>>(pos_emb, rw,  kr,  B_*POS_, H_, H_, nullptr, nullptr);

    // bias dot vectors
    bias_dot<<<(B_*S_*NH_*32 + 255) / 256, 256>>>(kvh, r_w_bias, rwb, S_);
    bias_dot<<<(B_*POS_*NH_*32 + 255) / 256, 256>>>(kr, r_r_bias, rrb, POS_);

    // fused attention (MMA: ac + shifted bd + mask + softmax + P@V)
    flash_mma<<<dim3(S_/64, NH_, B_), 256, smem>>>(mask);

    // output projection + bias + residual + exact GELU (tf32 MMA)
    gemm_tf32<true><<<dim3(12, 32), 256>>>(ctx, w_out, out, B_*S_, H_, H_, b_out, hidden);
}

// round 3
// speedup vs baseline: 2.9413x; 1.8927x over previous
#include <cuda_runtime.h>
#include <cuda_bf16.h>
#include <math.h>
#include <stdint.h>

#define B_   4
#define S_   1024
#define H_   768
#define NH_  12
#define DH_  64
#define POS_ 2048

// ---------------- scratch (static device arrays; no allocations) ----------------
__device__ __nv_bfloat16 g_qh [B_*S_*H_];     // (B,S,NH,DH)
__device__ __nv_bfloat16 g_kvh[B_*S_*H_];     // (B,S,NH,DH)
__device__ __nv_bfloat16 g_kr [B_*POS_*H_];   // (B,POS,NH,DH)
__device__ float g_rwb[B_*NH_*S_];
__device__ float g_rrb[B_*NH_*POS_];
__device__ float g_ctx[B_*S_*H_];             // attention output fp32

// ---------------- PTX helpers ---------------------------------------------------
__device__ __forceinline__ uint32_t sptr(const void* p) {
    return (uint32_t)__cvta_generic_to_shared(p);
}
__device__ __forceinline__ void ldsm4(uint32_t* r, uint32_t a) {
    asm volatile("ldmatrix.sync.aligned.m8n8.x4.shared.b16 {%0,%1,%2,%3},[%4];"
                 : "=r"(r[0]), "=r"(r[1]), "=r"(r[2]), "=r"(r[3]) : "r"(a));
}
__device__ __forceinline__ void ldsm4t(uint32_t* r, uint32_t a) {
    asm volatile("ldmatrix.sync.aligned.m8n8.x4.trans.shared.b16 {%0,%1,%2,%3},[%4];"
                 : "=r"(r[0]), "=r"(r[1]), "=r"(r[2]), "=r"(r[3]) : "r"(a));
}
__device__ __forceinline__ void mma16816(float* d, const uint32_t* a, const uint32_t* b) {
    asm volatile(
        "mma.sync.aligned.m16n8k16.row.col.f32.bf16.bf16.f32 "
        "{%0,%1,%2,%3},{%4,%5,%6,%7},{%8,%9},{%0,%1,%2,%3};"
        : "+f"(d[0]), "+f"(d[1]), "+f"(d[2]), "+f"(d[3])
        : "r"(a[0]), "r"(a[1]), "r"(a[2]), "r"(a[3]), "r"(b[0]), "r"(b[1]));
}

// ---------------- bf16 MMA GEMM: C = A(MxK,f32) @ B(KxN,f32) --------------------
// Block 128m x 64n x 64k, 256 threads, warps 4m x 2n, warp tile 32x32.
#define GLA_ 72   // A smem stride in halves ([m][k], k=64 +8 pad)
#define GLB_ 72   // B smem stride in halves ([k][n], n=64 +8 pad)
template<typename TC, bool EPI>
__global__ __launch_bounds__(256) void gemm_bf16(
    const float* __restrict__ A, const float* __restrict__ Bm,
    TC* __restrict__ C, int M, int N, int K,
    const float* __restrict__ bias, const float* __restrict__ resid)
{
    __shared__ __align__(16) __nv_bfloat16 As[128 * GLA_];
    __shared__ __align__(16) __nv_bfloat16 Bs[64 * GLB_];
    const int tid = threadIdx.x;
    const int m0 = blockIdx.y * 128, n0 = blockIdx.x * 64;
    const int wid = tid >> 5, lane = tid & 31;
    const int wm = wid & 3, wn = wid >> 2;
    const int g = lane >> 2, tig = lane & 3;

    float acc[2][4][4];
#pragma unroll
    for (int mi = 0; mi < 2; mi++)
#pragma unroll
        for (int ni = 0; ni < 4; ni++)
#pragma unroll
            for (int e = 0; e < 4; e++) acc[mi][ni][e] = 0.f;

    const uint32_t a_base = sptr(As) + (((wm * 32 + (lane & 15)) * GLA_ + (lane >> 4) * 8) << 1);
    const uint32_t b_base = sptr(Bs) + ((((lane & 15)) * GLB_ + wn * 32 + (lane >> 4) * 8) << 1);

    for (int k0 = 0; k0 < K; k0 += 64) {
        // load A tile [128][64]
#pragma unroll
        for (int it = 0; it < 8; it++) {
            const int idx = tid + it * 256;
            const int r = idx >> 4, c4 = (idx & 15) * 4;
            float4 v = *(const float4*)&A[(size_t)(m0 + r) * K + k0 + c4];
            __nv_bfloat162 h0 = __float22bfloat162_rn(make_float2(v.x, v.y));
            __nv_bfloat162 h1 = __float22bfloat162_rn(make_float2(v.z, v.w));
            *(__nv_bfloat162*)&As[r * GLA_ + c4]     = h0;
            *(__nv_bfloat162*)&As[r * GLA_ + c4 + 2] = h1;
        }
        // load B tile [64][64]
#pragma unroll
        for (int it = 0; it < 4; it++) {
            const int idx = tid + it * 256;
            const int k = idx >> 4, c4 = (idx & 15) * 4;
            float4 v = *(const float4*)&Bm[(size_t)(k0 + k) * N + n0 + c4];
            __nv_bfloat162 h0 = __float22bfloat162_rn(make_float2(v.x, v.y));
            __nv_bfloat162 h1 = __float22bfloat162_rn(make_float2(v.z, v.w));
            *(__nv_bfloat162*)&Bs[k * GLB_ + c4]     = h0;
            *(__nv_bfloat162*)&Bs[k * GLB_ + c4 + 2] = h1;
        }
        __syncthreads();
#pragma unroll
        for (int kc = 0; kc < 4; kc++) {
            const int kb = kc * 16;
            uint32_t af[2][4];
            ldsm4(af[0], a_base + (kb << 1));
            ldsm4(af[1], a_base + ((16 * GLA_ + kb) << 1));
            uint32_t bf[2][4];
            ldsm4t(bf[0], b_base + ((kb * GLB_) << 1));
            ldsm4t(bf[1], b_base + ((kb * GLB_ + 16) << 1));
#pragma unroll
            for (int mi = 0; mi < 2; mi++)
#pragma unroll
                for (int nn = 0; nn < 2; nn++) {
                    mma16816(acc[mi][nn * 2 + 0], af[mi], &bf[nn][0]);
                    mma16816(acc[mi][nn * 2 + 1], af[mi], &bf[nn][2]);
                }
        }
        __syncthreads();
    }
#pragma unroll
    for (int mi = 0; mi < 2; mi++) {
#pragma unroll
        for (int ni = 0; ni < 4; ni++) {
            const int row = m0 + wm * 32 + mi * 16 + g;
            const int col = n0 + wn * 32 + ni * 8 + 2 * tig;
#pragma unroll
            for (int half = 0; half < 2; half++) {
                const int r = row + half * 8;
                float v0 = acc[mi][ni][half * 2 + 0];
                float v1 = acc[mi][ni][half * 2 + 1];
                if (EPI) {
                    float x0 = v0 + bias[col]     + resid[(size_t)r * N + col];
                    float x1 = v1 + bias[col + 1] + resid[(size_t)r * N + col + 1];
                    v0 = 0.5f * x0 * (1.f + erff(x0 * 0.70710678118654752f));
                    v1 = 0.5f * x1 * (1.f + erff(x1 * 0.70710678118654752f));
                }
                if (sizeof(TC) == 2) {
                    __nv_bfloat162 h = __float22bfloat162_rn(make_float2(v0, v1));
                    *(__nv_bfloat162*)&C[(size_t)r * N + col] = h;
                } else {
                    float* cp = (float*)&C[(size_t)r * N + col];
                    cp[0] = v0; cp[1] = v1;
                }
            }
        }
    }
}

// ---- per-(b,pos,head) bias dots ------------------------------------------------
__global__ void bias_dot(const __nv_bfloat16* __restrict__ X, const float* __restrict__ w,
                         float* __restrict__ out, int L)
{
    const int gidx = blockIdx.x * (blockDim.x >> 5) + (threadIdx.x >> 5);
    const int lane = threadIdx.x & 31;
    if (gidx >= B_ * L * NH_) return;
    const int n = gidx % NH_;
    const int j = (gidx / NH_) % L;
    const int b = gidx / (NH_ * L);
    const __nv_bfloat16* x = X + ((size_t)((size_t)b * L + j) * NH_ + n) * DH_;
    const float* ww = w + n * DH_;
    float v = __bfloat162float(x[lane]) * ww[lane]
            + __bfloat162float(x[lane + 32]) * ww[lane + 32];
#pragma unroll
    for (int off = 16; off; off >>= 1) v += __shfl_xor_sync(0xffffffffu, v, off);
    if (!lane) out[((size_t)b * NH_ + n) * L + j] = v;
}

// ---------------- bf16 MMA flash attention with folded rel_shift ----------------
#define LH_ 72    // bf16 tile stride (halves)
#define LS_ 68    // S fp32 stride
#define LG_ 132   // G fp32 stride
__global__ __launch_bounds__(256) void flash_mma(const float* __restrict__ mask)
{
    extern __shared__ __align__(16) char smraw[];
    __nv_bfloat16* hb  = (__nv_bfloat16*)smraw;
    __nv_bfloat16* q_s  = hb;            // 64 x LH_   [i][d]
    __nv_bfloat16* kv_s = hb + 4608;     // 64 x LH_   [j][d]
    __nv_bfloat16* kr_s = hb + 9216;     // 128 x LH_  [t][d]
    __nv_bfloat16* p_s  = hb + 18432;    // 64 x LH_   [i][j]
    float* s_s = (float*)(hb + 23040);   // 64 x LS_
    float* g_s = s_s + 64 * LS_;         // 64 x LG_
    float* m_s = g_s + 64 * LG_;
    float* l_s = m_s + 64;
    float* c_s = l_s + 64;

    const int b = blockIdx.z, n = blockIdx.y;
    const int i0 = blockIdx.x * 64;
    const int tid = threadIdx.x;
    const int wid = tid >> 5, lane = tid & 31;
    const int wm = wid & 3, wn = wid >> 2;
    const int g = lane >> 2, tig = lane & 3;
    const int mr = wm * 16;

    // load Q tile (bf16 copy)
#pragma unroll
    for (int it = 0; it < 2; it++) {
        const int idx = tid + it * 256;
        const int r = idx >> 3, c8 = (idx & 7) * 8;
        uint4 v = *(const uint4*)&g_qh[(((size_t)b * S_ + i0 + r) * NH_ + n) * DH_ + c8];
        *(uint4*)&q_s[r * LH_ + c8] = v;
    }
    if (tid < 64) { m_s[tid] = -1e30f; l_s[tid] = 0.f; }
    if (tid < 36) ((uint32_t*)&kr_s[127 * LH_])[tid] = 0;  // zero pad row

    float acc_o[4][4];
#pragma unroll
    for (int ni = 0; ni < 4; ni++)
#pragma unroll
        for (int e = 0; e < 4; e++) acc_o[ni][e] = 0.f;

    const float* rwb_bn = g_rwb + ((size_t)b * NH_ + n) * S_;
    const float* rrb_bn = g_rrb + ((size_t)b * NH_ + n) * POS_;

    // per-warp ldmatrix base addresses
    const uint32_t qa  = sptr(q_s)  + (((mr + (lane & 15)) * LH_ + (lane >> 4) * 8) << 1);
    const uint32_t pa  = sptr(p_s)  + (((mr + (lane & 15)) * LH_ + (lane >> 4) * 8) << 1);
    const uint32_t kvn = sptr(kv_s) + ((((lane >> 4) * 8 + (lane & 7)) * LH_ + ((lane >> 3) & 1) * 8) << 1);
    const uint32_t krn = sptr(kr_s) + ((((lane >> 4) * 8 + (lane & 7)) * LH_ + ((lane >> 3) & 1) * 8) << 1);
    const uint32_t kvt = sptr(kv_s) + (((lane & 15) * LH_ + (lane >> 4) * 8) << 1);

    for (int jt = 0; jt < 16; ++jt) {
        const int j0 = jt * 64;
        const int pbase = 1024 + j0 - i0 - 63;
        __syncthreads();
        // load KV tile
#pragma unroll
        for (int it = 0; it < 2; it++) {
            const int idx = tid + it * 256;
            const int r = idx >> 3, c8 = (idx & 7) * 8;
            uint4 v = *(const uint4*)&g_kvh[(((size_t)b * S_ + j0 + r) * NH_ + n) * DH_ + c8];
            *(uint4*)&kv_s[r * LH_ + c8] = v;
        }
        // load KR window (127 rows)
        for (int idx = tid; idx < 127 * 8; idx += 256) {
            const int r = idx >> 3, c8 = (idx & 7) * 8;
            uint4 v = *(const uint4*)&g_kr[(((size_t)b * POS_ + pbase + r) * NH_ + n) * DH_ + c8];
            *(uint4*)&kr_s[r * LH_ + c8] = v;
        }
        __syncthreads();

        // ---- S (64x64) and G (64x128) via MMA ----
        float acc_s[4][4], acc_g[8][4];
#pragma unroll
        for (int ni = 0; ni < 4; ni++)
#pragma unroll
            for (int e = 0; e < 4; e++) acc_s[ni][e] = 0.f;
#pragma unroll
        for (int ni = 0; ni < 8; ni++)
#pragma unroll
            for (int e = 0; e < 4; e++) acc_g[ni][e] = 0.f;

#pragma unroll
        for (int kc = 0; kc < 4; kc++) {
            const int kb = kc * 16;
            uint32_t af[4];
            ldsm4(af, qa + (kb << 1));
#pragma unroll
            for (int nn = 0; nn < 2; nn++) {
                uint32_t bf[4];
                ldsm4(bf, kvn + (((wn * 32 + nn * 16) * LH_ + kb) << 1));
                mma16816(acc_s[nn * 2 + 0], af, &bf[0]);
                mma16816(acc_s[nn * 2 + 1], af, &bf[2]);
            }
#pragma unroll
            for (int nn = 0; nn < 4; nn++) {
                uint32_t bf[4];
                ldsm4(bf, krn + (((wn * 64 + nn * 16) * LH_ + kb) << 1));
                mma16816(acc_g[nn * 2 + 0], af, &bf[0]);
                mma16816(acc_g[nn * 2 + 1], af, &bf[2]);
            }
        }
        // scatter accumulators to smem
        {
            const int r0 = mr + g;
#pragma unroll
            for (int ni = 0; ni < 4; ni++) {
                const int c = wn * 32 + ni * 8 + 2 * tig;
                s_s[r0 * LS_ + c]           = acc_s[ni][0];
                s_s[r0 * LS_ + c + 1]       = acc_s[ni][1];
                s_s[(r0 + 8) * LS_ + c]     = acc_s[ni][2];
                s_s[(r0 + 8) * LS_ + c + 1] = acc_s[ni][3];
            }
#pragma unroll
            for (int ni = 0; ni < 8; ni++) {
                const int c = wn * 64 + ni * 8 + 2 * tig;
                g_s[r0 * LG_ + c]           = acc_g[ni][0];
                g_s[r0 * LG_ + c + 1]       = acc_g[ni][1];
                g_s[(r0 + 8) * LG_ + c]     = acc_g[ni][2];
                g_s[(r0 + 8) * LG_ + c + 1] = acc_g[ni][3];
            }
        }
        __syncthreads();

        // ---- softmax: 4 threads per row, 16 cols each ----
        {
            const int row = tid >> 2, qq = tid & 3;
            const int gi = i0 + row;
            const float mo = m_s[row], lo = l_s[row];
            const float* mrow = mask + ((size_t)b * S_ + gi) * S_ + j0 + qq * 16;
            const float* rwb4 = rwb_bn + j0 + qq * 16;
            float vbuf[16];
            float rmax = -1e30f;
#pragma unroll
            for (int c = 0; c < 16; c++) {
                const int col = qq * 16 + c;
                const float sv = s_s[row * LS_ + col];
                const float gv = g_s[row * LG_ + col - row + 63];
                const float v = (sv + gv + rwb4[c] + rrb_bn[1024 + j0 + col - gi]) * 0.125f
                                + mrow[c] * (-65500.0f);
                vbuf[c] = v;
                rmax = fmaxf(rmax, v);
            }
            rmax = fmaxf(rmax, __shfl_xor_sync(0xffffffffu, rmax, 1));
            rmax = fmaxf(rmax, __shfl_xor_sync(0xffffffffu, rmax, 2));
            const float mn = fmaxf(mo, rmax);
            const float corr = __expf(mo - mn);
            float ls = 0.f;
#pragma unroll
            for (int c = 0; c < 16; c += 2) {
                const float p0 = __expf(vbuf[c] - mn);
                const float p1 = __expf(vbuf[c + 1] - mn);
                ls += p0 + p1;
                __nv_bfloat162 h = __float22bfloat162_rn(make_float2(p0, p1));
                *(__nv_bfloat162*)&p_s[row * LH_ + qq * 16 + c] = h;
            }
            ls += __shfl_xor_sync(0xffffffffu, ls, 1);
            ls += __shfl_xor_sync(0xffffffffu, ls, 2);
            if (qq == 0) { m_s[row] = mn; l_s[row] = lo * corr + ls; c_s[row] = corr; }
        }
        __syncthreads();

        // ---- rescale O, then O += P @ V via MMA ----
        {
            const float cr0 = c_s[mr + g], cr1 = c_s[mr + g + 8];
#pragma unroll
            for (int ni = 0; ni < 4; ni++) {
                acc_o[ni][0] *= cr0; acc_o[ni][1] *= cr0;
                acc_o[ni][2] *= cr1; acc_o[ni][3] *= cr1;
            }
        }
#pragma unroll
        for (int kc = 0; kc < 4; kc++) {
            const int kb = kc * 16;
            uint32_t af[4];
            ldsm4(af, pa + (kb << 1));
#pragma unroll
            for (int nn = 0; nn < 2; nn++) {
                uint32_t bf[4];
                ldsm4t(bf, kvt + ((kb * LH_ + wn * 32 + nn * 16) << 1));
                mma16816(acc_o[nn * 2 + 0], af, &bf[0]);
                mma16816(acc_o[nn * 2 + 1], af, &bf[2]);
            }
        }
    }

    // ---- normalize and store (fp32 ctx) ----
    {
        const float inv0 = 1.f / l_s[mr + g];
        const float inv1 = 1.f / l_s[mr + g + 8];
        const size_t base0 = (((size_t)b * S_ + i0 + mr + g) * NH_ + n) * (size_t)DH_;
        const size_t base1 = (((size_t)b * S_ + i0 + mr + g + 8) * NH_ + n) * (size_t)DH_;
#pragma unroll
        for (int ni = 0; ni < 4; ni++) {
            const int col = wn * 32 + ni * 8 + 2 * tig;
            g_ctx[base0 + col]     = acc_o[ni][0] * inv0;
            g_ctx[base0 + col + 1] = acc_o[ni][1] * inv0;
            g_ctx[base1 + col]     = acc_o[ni][2] * inv1;
            g_ctx[base1 + col + 1] = acc_o[ni][3] * inv1;
        }
    }
}

// -------------------------------- launch ---------------------------------------
extern "C" void kernel_launch(void* const* d_in, const int* in_sizes, int n_in,
                              void* d_out, int out_size)
{
    const float* hidden   = (const float*)d_in[0];
    const float* pos_emb  = (const float*)d_in[1];
    const float* mask     = (const float*)d_in[2];
    const float* qw       = (const float*)d_in[3];
    const float* kvw      = (const float*)d_in[4];
    const float* rw       = (const float*)d_in[5];
    const float* r_r_bias = (const float*)d_in[6];
    const float* r_w_bias = (const float*)d_in[7];
    const float* w_out    = (const float*)d_in[8];
    const float* b_out    = (const float*)d_in[9];
    float* out = (float*)d_out;

    __nv_bfloat16 *qh, *kvh, *kr;
    float *rwb, *rrb, *ctx;
    cudaGetSymbolAddress((void**)&qh,  g_qh);
    cudaGetSymbolAddress((void**)&kvh, g_kvh);
    cudaGetSymbolAddress((void**)&kr,  g_kr);
    cudaGetSymbolAddress((void**)&rwb, g_rwb);
    cudaGetSymbolAddress((void**)&rrb, g_rrb);
    cudaGetSymbolAddress((void**)&ctx, g_ctx);

    const int smem = 23040 * 2 + (64 * LS_ + 64 * LG_ + 192) * (int)sizeof(float);
    cudaFuncSetAttribute(flash_mma, cudaFuncAttributeMaxDynamicSharedMemorySize, smem);

    // projections (bf16 MMA, bf16 outputs)
    gemm_bf16<__nv_bfloat16, false><<<dim3(12, 32), 256>>>(hidden,  qw,  qh,  B_*S_,   H_, H_, nullptr, nullptr);
    gemm_bf16<__nv_bfloat16, false><<<dim3(12, 32), 256>>>(hidden,  kvw, kvh, B_*S_,   H_, H_, nullptr, nullptr);
    gemm_bf16<__nv_bfloat16, false><<<dim3(12, 64), 256>>>(pos_emb, rw,  kr,  B_*POS_, H_, H_, nullptr, nullptr);

    // bias dot vectors
    bias_dot<<<(B_*S_*NH_*32 + 255) / 256, 256>>>(kvh, r_w_bias, rwb, S_);
    bias_dot<<<(B_*POS_*NH_*32 + 255) / 256, 256>>>(kr, r_r_bias, rrb, POS_);

    // fused attention
    flash_mma<<<dim3(S_/64, NH_, B_), 256, smem>>>(mask);

    // output projection + bias + residual + exact GELU (fp32 out)
    gemm_bf16<float, true><<<dim3(12, 32), 256>>>(ctx, w_out, out, B_*S_, H_, H_, b_out, hidden);
}

// round 4
// speedup vs baseline: 5.2290x; 1.7778x over previous
#include <cuda_runtime.h>
#include <cuda_bf16.h>
#include <math.h>
#include <stdint.h>

#define B_   4
#define S_   1024
#define H_   768
#define NH_  12
#define DH_  64
#define POS_ 2048

// ---------------- scratch (static device arrays; no allocations) ----------------
__device__ __nv_bfloat16 g_hidb[B_*S_*H_];
__device__ __nv_bfloat16 g_posb[B_*POS_*H_];
__device__ __nv_bfloat16 g_qwb [H_*H_];
__device__ __nv_bfloat16 g_kvwb[H_*H_];
__device__ __nv_bfloat16 g_rwgt[H_*H_];
__device__ __nv_bfloat16 g_wob [H_*H_];
__device__ __nv_bfloat16 g_qh [B_*S_*H_];
__device__ __nv_bfloat16 g_kvh[B_*S_*H_];
__device__ __nv_bfloat16 g_kr [B_*POS_*H_];
__device__ __nv_bfloat16 g_ctx[B_*S_*H_];

// ---------------- PTX helpers ---------------------------------------------------
__device__ __forceinline__ uint32_t sptr(const void* p) {
    return (uint32_t)__cvta_generic_to_shared(p);
}
__device__ __forceinline__ void ldsm4(uint32_t* r, uint32_t a) {
    asm volatile("ldmatrix.sync.aligned.m8n8.x4.shared.b16 {%0,%1,%2,%3},[%4];"
                 : "=r"(r[0]), "=r"(r[1]), "=r"(r[2]), "=r"(r[3]) : "r"(a));
}
__device__ __forceinline__ void ldsm4t(uint32_t* r, uint32_t a) {
    asm volatile("ldmatrix.sync.aligned.m8n8.x4.trans.shared.b16 {%0,%1,%2,%3},[%4];"
                 : "=r"(r[0]), "=r"(r[1]), "=r"(r[2]), "=r"(r[3]) : "r"(a));
}
__device__ __forceinline__ void mma16816(float* d, const uint32_t* a, const uint32_t* b) {
    asm volatile(
        "mma.sync.aligned.m16n8k16.row.col.f32.bf16.bf16.f32 "
        "{%0,%1,%2,%3},{%4,%5,%6,%7},{%8,%9},{%0,%1,%2,%3};"
        : "+f"(d[0]), "+f"(d[1]), "+f"(d[2]), "+f"(d[3])
        : "r"(a[0]), "r"(a[1]), "r"(a[2]), "r"(a[3]), "r"(b[0]), "r"(b[1]));
}
__device__ __forceinline__ void cpa16(uint32_t dst, const void* src) {
    asm volatile("cp.async.cg.shared.global [%0], [%1], 16;" :: "r"(dst), "l"(src));
}
__device__ __forceinline__ void cp_commit() {
    asm volatile("cp.async.commit_group;");
}
__device__ __forceinline__ void cp_wait0() {
    asm volatile("cp.async.wait_group 0;");
}
__device__ __forceinline__ uint32_t packbf(float a, float b) {
    __nv_bfloat162 h = __float22bfloat162_rn(make_float2(a, b));
    return *(uint32_t*)&h;
}

// ---------------- fp32 -> bf16 conversion (all tensors, one kernel) -------------
__global__ void convert_all(const float* __restrict__ h, const float* __restrict__ p,
                            const float* __restrict__ qw, const float* __restrict__ kvw,
                            const float* __restrict__ rw, const float* __restrict__ wo)
{
    const int N1 = 786432;            // hidden  (float4 units)
    const int N2 = N1 + 1572864;      // pos_emb
    const int N3 = N2 + 147456;       // qw
    const int N4 = N3 + 147456;       // kvw
    const int N5 = N4 + 147456;       // rw
    const int N6 = N5 + 147456;       // wo
    for (int i = blockIdx.x * blockDim.x + threadIdx.x; i < N6;
         i += gridDim.x * blockDim.x) {
        const float* src; __nv_bfloat16* dst; int li;
        if      (i < N1) { src = h;   dst = g_hidb; li = i; }
        else if (i < N2) { src = p;   dst = g_posb; li = i - N1; }
        else if (i < N3) { src = qw;  dst = g_qwb;  li = i - N2; }
        else if (i < N4) { src = kvw; dst = g_kvwb; li = i - N3; }
        else if (i < N5) { src = rw;  dst = g_rwgt; li = i - N4; }
        else             { src = wo;  dst = g_wob;  li = i - N5; }
        float4 v = ((const float4*)src)[li];
        uint2 u;
        u.x = packbf(v.x, v.y);
        u.y = packbf(v.z, v.w);
        ((uint2*)dst)[li] = u;
    }
}

// ---------------- bf16 GEMM, cp.async double-buffered 128x128x64 ----------------
#define GAST 9216   // A stage halves (128*72)
#define GBST 8704   // B stage halves (64*136)
__device__ __forceinline__ void gemm_load(int tid, const __nv_bfloat16* A,
    const __nv_bfloat16* Bm, int K, int N, int m0, int n0, int k0,
    uint32_t abase, uint32_t bbase)
{
#pragma unroll
    for (int it = 0; it < 4; it++) {
        const int id = tid + it * 256;
        const int r = id >> 3, c = (id & 7) * 8;
        cpa16(abase + (r * 72 + c) * 2, &A[(size_t)(m0 + r) * K + k0 + c]);
    }
#pragma unroll
    for (int it = 0; it < 4; it++) {
        const int id = tid + it * 256;
        const int r = id >> 4, c = (id & 15) * 8;
        cpa16(bbase + (r * 136 + c) * 2, &Bm[(size_t)(k0 + r) * N + n0 + c]);
    }
    cp_commit();
}

template<typename TC, bool EPI>
__global__ __launch_bounds__(256) void gemm_bf16(
    const __nv_bfloat16* __restrict__ A, const __nv_bfloat16* __restrict__ Bm,
    TC* __restrict__ C, int M, int N, int K,
    const float* __restrict__ bias, const float* __restrict__ resid)
{
    extern __shared__ __align__(16) __nv_bfloat16 gsm[];
    __nv_bfloat16* As = gsm;               // 2 stages of 128x72
    __nv_bfloat16* Bs = gsm + 2 * GAST;    // 2 stages of 64x136
    const int tid = threadIdx.x;
    const int m0 = blockIdx.y * 128, n0 = blockIdx.x * 128;
    const int wid = tid >> 5, lane = tid & 31;
    const int wm = wid & 1, wn = wid >> 1;
    const int g = lane >> 2, tig = lane & 3;

    const uint32_t asm0 = sptr(As), bsm0 = sptr(Bs);
    gemm_load(tid, A, Bm, K, N, m0, n0, 0, asm0, bsm0);

    float acc[4][4][4];
#pragma unroll
    for (int mi = 0; mi < 4; mi++)
#pragma unroll
        for (int nt = 0; nt < 4; nt++)
#pragma unroll
            for (int e = 0; e < 4; e++) acc[mi][nt][e] = 0.f;

    const uint32_t a_base = asm0 + (((wm * 64 + (lane & 15)) * 72 + (lane >> 4) * 8) << 1);
    const uint32_t b_base = bsm0 + ((((lane & 15)) * 136 + wn * 32 + (lane >> 4) * 8) << 1);

    const int KI = K >> 6;
    for (int ki = 0; ki < KI; ki++) {
        cp_wait0();
        __syncthreads();
        if (ki + 1 < KI)
            gemm_load(tid, A, Bm, K, N, m0, n0, (ki + 1) * 64,
                      asm0 + (((ki + 1) & 1) * GAST << 1),
                      bsm0 + (((ki + 1) & 1) * GBST << 1));
        const uint32_t ao = ((ki & 1) * GAST) << 1;
        const uint32_t bo = ((ki & 1) * GBST) << 1;
#pragma unroll
        for (int kc = 0; kc < 4; kc++) {
            uint32_t af[4][4], bv[2][4];
#pragma unroll
            for (int mi = 0; mi < 4; mi++)
                ldsm4(af[mi], a_base + ao + ((mi * 16 * 72 + kc * 16) << 1));
#pragma unroll
            for (int nn = 0; nn < 2; nn++)
                ldsm4t(bv[nn], b_base + bo + ((kc * 16 * 136 + nn * 16) << 1));
#pragma unroll
            for (int mi = 0; mi < 4; mi++)
#pragma unroll
                for (int nn = 0; nn < 2; nn++) {
                    mma16816(acc[mi][2 * nn + 0], af[mi], &bv[nn][0]);
                    mma16816(acc[mi][2 * nn + 1], af[mi], &bv[nn][2]);
                }
        }
        __syncthreads();
    }

#pragma unroll
    for (int mi = 0; mi < 4; mi++) {
#pragma unroll
        for (int nt = 0; nt < 4; nt++) {
            const int col = n0 + wn * 32 + nt * 8 + 2 * tig;
#pragma unroll
            for (int half = 0; half < 2; half++) {
                const int r = m0 + wm * 64 + mi * 16 + g + half * 8;
                float v0 = acc[mi][nt][half * 2 + 0];
                float v1 = acc[mi][nt][half * 2 + 1];
                if (EPI) {
                    float x0 = v0 + bias[col]     + resid[(size_t)r * N + col];
                    float x1 = v1 + bias[col + 1] + resid[(size_t)r * N + col + 1];
                    v0 = 0.5f * x0 * (1.f + erff(x0 * 0.70710678118654752f));
                    v1 = 0.5f * x1 * (1.f + erff(x1 * 0.70710678118654752f));
                    float* cp = (float*)&C[(size_t)r * N + col];
                    cp[0] = v0; cp[1] = v1;
                } else {
                    *(uint32_t*)&C[(size_t)r * N + col] = packbf(v0, v1);
                }
            }
        }
    }
}

// ---------------- FA2-style flash attention with folded rel_shift ---------------
// 128 query rows per block, 8 warps x 16 rows (full 64 key cols each).
// S via qw_s@kv^T; banded G via qr_s@kr_window^T (only ~10 n-tiles per warp),
// scattered pre-shifted into per-warp smem; softmax + P entirely in registers.
#define FLH 72
#define FGS 68
__device__ __forceinline__ void flash_load(int tid, int b, int n, int i0, int jt,
                                           uint32_t kvb, uint32_t krb)
{
    const int j0 = jt * 64;
    const int pb = 1024 + j0 - i0 - 127;
#pragma unroll
    for (int it = 0; it < 2; it++) {
        const int id = tid + it * 256;
        const int r = id >> 3, c = (id & 7) * 8;
        cpa16(kvb + (r * FLH + c) * 2,
              &g_kvh[(((size_t)b * S_ + j0 + r) * NH_ + n) * DH_ + c]);
    }
#pragma unroll
    for (int it = 0; it < 6; it++) {
        const int id = tid + it * 256;
        const int r = id >> 3, c = (id & 7) * 8;
        if (r < 191)
            cpa16(krb + (r * FLH + c) * 2,
                  &g_kr[(((size_t)b * POS_ + pb + r) * NH_ + n) * DH_ + c]);
    }
    cp_commit();
}

__global__ __launch_bounds__(256) void flash_mma(const float* __restrict__ mask,
    const float* __restrict__ rwbias, const float* __restrict__ rrbias)
{
    extern __shared__ __align__(16) char smraw[];
    __nv_bfloat16* qw_s = (__nv_bfloat16*)smraw;        // 128 x 72
    __nv_bfloat16* qr_s = qw_s + 128 * FLH;             // 128 x 72
    __nv_bfloat16* kv_s = qr_s + 128 * FLH;             // 2 x 64 x 72
    __nv_bfloat16* kr_s = kv_s + 2 * 64 * FLH;          // 2 x 192 x 72
    float* gsh = (float*)(kr_s + 2 * 192 * FLH);        // 8 x 16 x 68
    float* bw  = gsh + 8 * 16 * FGS;                    // 64
    float* br  = bw + 64;                               // 64

    const int b = blockIdx.z, n = blockIdx.y;
    const int i0 = blockIdx.x * 128;
    const int tid = threadIdx.x;
    const int w = tid >> 5, lane = tid & 31;
    const int g = lane >> 2, tig = lane & 3;

    if (tid < 64)       bw[tid]      = rwbias[n * DH_ + tid];
    else if (tid < 128) br[tid - 64] = rrbias[n * DH_ + tid - 64];
    if (tid < 72) {  // zero kr row 191 in both stages (never loaded, may feed MMA)
        const int st = tid / 36, idx = tid % 36;
        ((uint32_t*)(kr_s + st * 192 * FLH + 191 * FLH))[idx] = 0;
    }
    __syncthreads();

    // prefetch first key tile
    const uint32_t kvsm = sptr(kv_s), krsm = sptr(kr_s);
    flash_load(tid, b, n, i0, 0, kvsm, krsm);

    // build biased Q tiles
#pragma unroll
    for (int it = 0; it < 4; it++) {
        const int id = tid + it * 256;
        const int r = id >> 3, c = (id & 7) * 8;
        uint4 v = *(const uint4*)&g_qh[(((size_t)b * S_ + i0 + r) * NH_ + n) * DH_ + c];
        __nv_bfloat162* hp = (__nv_bfloat162*)&v;
        uint4 ow, orr;
        uint32_t* wp = (uint32_t*)&ow;
        uint32_t* rp = (uint32_t*)&orr;
#pragma unroll
        for (int k = 0; k < 4; k++) {
            float2 f = __bfloat1622float2(hp[k]);
            wp[k] = packbf(f.x + bw[c + 2 * k], f.y + bw[c + 2 * k + 1]);
            rp[k] = packbf(f.x + br[c + 2 * k], f.y + br[c + 2 * k + 1]);
        }
        *(uint4*)&qw_s[r * FLH + c] = ow;
        *(uint4*)&qr_s[r * FLH + c] = orr;
    }

    const uint32_t qwa = sptr(qw_s) + (((16 * w + (lane & 15)) * FLH + (lane >> 4) * 8) << 1);
    const uint32_t qra = qwa + (128 * FLH << 1);
    const uint32_t kvn = kvsm + (((((lane >> 4) * 8 + (lane & 7)) * FLH) + ((lane >> 3) & 1) * 8) << 1);
    const uint32_t krn = krsm + (((((lane >> 4) * 8 + (lane & 7)) * FLH) + ((lane >> 3) & 1) * 8) << 1);
    const uint32_t kvt = kvsm + ((((lane & 15)) * FLH + (lane >> 4) * 8) << 1);

    float m0v = -1e30f, m1v = -1e30f, l0v = 0.f, l1v = 0.f;
    float acc_o[8][4];
#pragma unroll
    for (int nt = 0; nt < 8; nt++)
#pragma unroll
        for (int e = 0; e < 4; e++) acc_o[nt][e] = 0.f;

    const int nt0 = 14 - 2 * w;
    float* gw = gsh + w * 16 * FGS;
    const int gi0 = i0 + 16 * w + g;
    const float* mrow0 = mask + ((size_t)b * S_ + gi0) * S_;
    const float* mrow1 = mrow0 + 8 * S_;

    for (int jt = 0; jt < 16; jt++) {
        cp_wait0();
        __syncthreads();
        if (jt < 15)
            flash_load(tid, b, n, i0, jt + 1,
                       kvsm + (((jt + 1) & 1) * 64 * FLH << 1),
                       krsm + (((jt + 1) & 1) * 192 * FLH << 1));
        const uint32_t kvo = ((jt & 1) * 64 * FLH) << 1;
        const uint32_t kro = ((jt & 1) * 192 * FLH) << 1;
        const int j0 = jt * 64;

        // ---- S = Qw @ KV^T ----
        float acc_s[8][4];
#pragma unroll
        for (int nt = 0; nt < 8; nt++)
#pragma unroll
            for (int e = 0; e < 4; e++) acc_s[nt][e] = 0.f;
#pragma unroll
        for (int kc = 0; kc < 4; kc++) {
            uint32_t af[4];
            ldsm4(af, qwa + kc * 32);
#pragma unroll
            for (int nn = 0; nn < 4; nn++) {
                uint32_t bf[4];
                ldsm4(bf, kvn + kvo + (((nn * 16) * FLH + kc * 16) << 1));
                mma16816(acc_s[2 * nn + 0], af, &bf[0]);
                mma16816(acc_s[2 * nn + 1], af, &bf[2]);
            }
        }

        // ---- banded G = Qr @ KR^T, scatter pre-shifted ----
        uint32_t afr[4][4];
#pragma unroll
        for (int kc = 0; kc < 4; kc++) ldsm4(afr[kc], qra + kc * 32);
        __syncwarp();
#pragma unroll
        for (int np = 0; np < 5; np++) {
            const int tr = (nt0 + 2 * np) * 8;
            float ga[4] = {0.f, 0.f, 0.f, 0.f};
            float gb[4] = {0.f, 0.f, 0.f, 0.f};
#pragma unroll
            for (int kc = 0; kc < 4; kc++) {
                uint32_t bf[4];
                ldsm4(bf, krn + kro + ((tr * FLH + kc * 16) << 1));
                mma16816(ga, afr[kc], &bf[0]);
                mma16816(gb, afr[kc], &bf[2]);
            }
            const int base = tr + 2 * tig + 16 * w - 127;
            const int cA = base + g;       // row g,   tile tr
            const int cB = cA + 8;         // row g+8, tile tr
            if ((unsigned)cA < 64u)        gw[g * FGS + cA]             = ga[0];
            if ((unsigned)(cA + 1) < 64u)  gw[g * FGS + cA + 1]         = ga[1];
            if ((unsigned)cB < 64u)        gw[(g + 8) * FGS + cB]       = ga[2];
            if ((unsigned)(cB + 1) < 64u)  gw[(g + 8) * FGS + cB + 1]   = ga[3];
            const int cA2 = cA + 8;        // row g,   tile tr+8
            const int cB2 = cB + 8;
            if ((unsigned)cA2 < 64u)       gw[g * FGS + cA2]            = gb[0];
            if ((unsigned)(cA2 + 1) < 64u) gw[g * FGS + cA2 + 1]        = gb[1];
            if ((unsigned)cB2 < 64u)       gw[(g + 8) * FGS + cB2]      = gb[2];
            if ((unsigned)(cB2 + 1) < 64u) gw[(g + 8) * FGS + cB2 + 1]  = gb[3];
        }
        __syncwarp();

        // ---- add G, mask, scale; online softmax in registers ----
        float rmax0 = -1e30f, rmax1 = -1e30f;
#pragma unroll
        for (int nt = 0; nt < 8; nt++) {
#pragma unroll
            for (int e = 0; e < 2; e++) {
                const int col = nt * 8 + 2 * tig + e;
                float v0 = (acc_s[nt][e]     + gw[g * FGS + col])       * 0.125f
                           + mrow0[j0 + col] * (-65500.0f);
                float v1 = (acc_s[nt][2 + e] + gw[(g + 8) * FGS + col]) * 0.125f
                           + mrow1[j0 + col] * (-65500.0f);
                acc_s[nt][e] = v0; acc_s[nt][2 + e] = v1;
                rmax0 = fmaxf(rmax0, v0); rmax1 = fmaxf(rmax1, v1);
            }
        }
        rmax0 = fmaxf(rmax0, __shfl_xor_sync(0xffffffffu, rmax0, 1));
        rmax0 = fmaxf(rmax0, __shfl_xor_sync(0xffffffffu, rmax0, 2));
        rmax1 = fmaxf(rmax1, __shfl_xor_sync(0xffffffffu, rmax1, 1));
        rmax1 = fmaxf(rmax1, __shfl_xor_sync(0xffffffffu, rmax1, 2));
        const float mn0 = fmaxf(m0v, rmax0), mn1 = fmaxf(m1v, rmax1);
        const float cr0 = __expf(m0v - mn0), cr1 = __expf(m1v - mn1);
        m0v = mn0; m1v = mn1;
        float ls0 = 0.f, ls1 = 0.f;
#pragma unroll
        for (int nt = 0; nt < 8; nt++) {
#pragma unroll
            for (int e = 0; e < 2; e++) {
                const float p0 = __expf(acc_s[nt][e] - mn0);
                const float p1 = __expf(acc_s[nt][2 + e] - mn1);
                ls0 += p0; ls1 += p1;
                acc_s[nt][e] = p0; acc_s[nt][2 + e] = p1;
            }
        }
        ls0 += __shfl_xor_sync(0xffffffffu, ls0, 1);
        ls0 += __shfl_xor_sync(0xffffffffu, ls0, 2);
        ls1 += __shfl_xor_sync(0xffffffffu, ls1, 1);
        ls1 += __shfl_xor_sync(0xffffffffu, ls1, 2);
        l0v = l0v * cr0 + ls0;
        l1v = l1v * cr1 + ls1;

        // rescale O; pack P fragments (FA2 register repack, no smem)
        uint32_t pa[4][4];
#pragma unroll
        for (int kc = 0; kc < 4; kc++) {
            pa[kc][0] = packbf(acc_s[2 * kc][0],     acc_s[2 * kc][1]);
            pa[kc][1] = packbf(acc_s[2 * kc][2],     acc_s[2 * kc][3]);
            pa[kc][2] = packbf(acc_s[2 * kc + 1][0], acc_s[2 * kc + 1][1]);
            pa[kc][3] = packbf(acc_s[2 * kc + 1][2], acc_s[2 * kc + 1][3]);
        }
#pragma unroll
        for (int nt = 0; nt < 8; nt++) {
            acc_o[nt][0] *= cr0; acc_o[nt][1] *= cr0;
            acc_o[nt][2] *= cr1; acc_o[nt][3] *= cr1;
        }

        // ---- O += P @ V ----
#pragma unroll
        for (int kc = 0; kc < 4; kc++) {
#pragma unroll
            for (int nn = 0; nn < 4; nn++) {
                uint32_t bf[4];
                ldsm4t(bf, kvt + kvo + (((kc * 16) * FLH + nn * 16) << 1));
                mma16816(acc_o[2 * nn + 0], pa[kc], &bf[0]);
                mma16816(acc_o[2 * nn + 1], pa[kc], &bf[2]);
            }
        }
    }

    // ---- normalize and store (bf16 ctx) ----
    const float inv0 = 1.f / l0v, inv1 = 1.f / l1v;
    const size_t b0 = (((size_t)b * S_ + i0 + 16 * w + g) * NH_ + n) * (size_t)DH_;
    const size_t b1 = b0 + 8 * (size_t)NH_ * DH_;
#pragma unroll
    for (int nt = 0; nt < 8; nt++) {
        const int c = nt * 8 + 2 * tig;
        *(uint32_t*)&g_ctx[b0 + c] = packbf(acc_o[nt][0] * inv0, acc_o[nt][1] * inv0);
        *(uint32_t*)&g_ctx[b1 + c] = packbf(acc_o[nt][2] * inv1, acc_o[nt][3] * inv1);
    }
}

// -------------------------------- launch ---------------------------------------
extern "C" void kernel_launch(void* const* d_in, const int* in_sizes, int n_in,
                              void* d_out, int out_size)
{
    const float* hidden   = (const float*)d_in[0];
    const float* pos_emb  = (const float*)d_in[1];
    const float* mask     = (const float*)d_in[2];
    const float* qw       = (const float*)d_in[3];
    const float* kvw      = (const float*)d_in[4];
    const float* rw       = (const float*)d_in[5];
    const float* r_r_bias = (const float*)d_in[6];
    const float* r_w_bias = (const float*)d_in[7];
    const float* w_out    = (const float*)d_in[8];
    const float* b_out    = (const float*)d_in[9];
    float* out = (float*)d_out;

    __nv_bfloat16 *hidb, *posb, *qwb, *kvwb, *rwgt, *wob, *qh, *kvh, *kr, *ctx;
    cudaGetSymbolAddress((void**)&hidb, g_hidb);
    cudaGetSymbolAddress((void**)&posb, g_posb);
    cudaGetSymbolAddress((void**)&qwb,  g_qwb);
    cudaGetSymbolAddress((void**)&kvwb, g_kvwb);
    cudaGetSymbolAddress((void**)&rwgt, g_rwgt);
    cudaGetSymbolAddress((void**)&wob,  g_wob);
    cudaGetSymbolAddress((void**)&qh,   g_qh);
    cudaGetSymbolAddress((void**)&kvh,  g_kvh);
    cudaGetSymbolAddress((void**)&kr,   g_kr);
    cudaGetSymbolAddress((void**)&ctx,  g_ctx);

    const int gemm_smem  = (2 * GAST + 2 * GBST) * 2;     // 71680 B
    const int flash_smem = (2 * 128 * FLH + 2 * 64 * FLH + 2 * 192 * FLH) * 2
                           + (8 * 16 * FGS + 128) * 4;    // 145920 B
    cudaFuncSetAttribute(gemm_bf16<__nv_bfloat16, false>,
                         cudaFuncAttributeMaxDynamicSharedMemorySize, gemm_smem);
    cudaFuncSetAttribute(gemm_bf16<float, true>,
                         cudaFuncAttributeMaxDynamicSharedMemorySize, gemm_smem);
    cudaFuncSetAttribute(flash_mma,
                         cudaFuncAttributeMaxDynamicSharedMemorySize, flash_smem);

    // fp32 -> bf16 conversion of all GEMM inputs
    convert_all<<<2048, 256>>>(hidden, pos_emb, qw, kvw, rw, w_out);

    // projections (bf16, cp.async pipelined)
    gemm_bf16<__nv_bfloat16, false><<<dim3(6, 32), 256, gemm_smem>>>(
        hidb, qwb,  qh,  B_*S_,   H_, H_, nullptr, nullptr);
    gemm_bf16<__nv_bfloat16, false><<<dim3(6, 32), 256, gemm_smem>>>(
        hidb, kvwb, kvh, B_*S_,   H_, H_, nullptr, nullptr);
    gemm_bf16<__nv_bfloat16, false><<<dim3(6, 64), 256, gemm_smem>>>(
        posb, rwgt, kr,  B_*POS_, H_, H_, nullptr, nullptr);

    // fused attention (biases folded into Q tiles; rel_shift folded into G band)
    flash_mma<<<dim3(S_/128, NH_, B_), 256, flash_smem>>>(mask, r_w_bias, r_r_bias);

    // output projection + bias + residual + exact GELU
    gemm_bf16<float, true><<<dim3(6, 32), 256, gemm_smem>>>(
        ctx, wob, out, B_*S_, H_, H_, b_out, hidden);
}

// round 5
// speedup vs baseline: 5.7362x; 1.0970x over previous
#include <cuda_runtime.h>
#include <cuda_bf16.h>
#include <math.h>
#include <stdint.h>

#define B_   4
#define S_   1024
#define H_   768
#define NH_  12
#define DH_  64
#define POS_ 2048

// ---------------- scratch (static device arrays; no allocations) ----------------
__device__ __nv_bfloat16 g_hidb[B_*S_*H_];
__device__ __nv_bfloat16 g_posb[B_*POS_*H_];
__device__ __nv_bfloat16 g_qwb [H_*H_];
__device__ __nv_bfloat16 g_kvwb[H_*H_];
__device__ __nv_bfloat16 g_rwgt[H_*H_];
__device__ __nv_bfloat16 g_wob [H_*H_];
__device__ __nv_bfloat16 g_qh [B_*S_*H_];
__device__ __nv_bfloat16 g_kvh[B_*S_*H_];
__device__ __nv_bfloat16 g_kr [B_*POS_*H_];
__device__ __nv_bfloat16 g_ctx[B_*S_*H_];

// ---------------- PTX helpers ---------------------------------------------------
__device__ __forceinline__ uint32_t sptr(const void* p) {
    return (uint32_t)__cvta_generic_to_shared(p);
}
__device__ __forceinline__ void ldsm4(uint32_t* r, uint32_t a) {
    asm volatile("ldmatrix.sync.aligned.m8n8.x4.shared.b16 {%0,%1,%2,%3},[%4];"
                 : "=r"(r[0]), "=r"(r[1]), "=r"(r[2]), "=r"(r[3]) : "r"(a));
}
__device__ __forceinline__ void ldsm4t(uint32_t* r, uint32_t a) {
    asm volatile("ldmatrix.sync.aligned.m8n8.x4.trans.shared.b16 {%0,%1,%2,%3},[%4];"
                 : "=r"(r[0]), "=r"(r[1]), "=r"(r[2]), "=r"(r[3]) : "r"(a));
}
__device__ __forceinline__ void mma16816(float* d, const uint32_t* a, const uint32_t* b) {
    asm volatile(
        "mma.sync.aligned.m16n8k16.row.col.f32.bf16.bf16.f32 "
        "{%0,%1,%2,%3},{%4,%5,%6,%7},{%8,%9},{%0,%1,%2,%3};"
        : "+f"(d[0]), "+f"(d[1]), "+f"(d[2]), "+f"(d[3])
        : "r"(a[0]), "r"(a[1]), "r"(a[2]), "r"(a[3]), "r"(b[0]), "r"(b[1]));
}
__device__ __forceinline__ void cpa16(uint32_t dst, const void* src) {
    asm volatile("cp.async.cg.shared.global [%0], [%1], 16;" :: "r"(dst), "l"(src));
}
__device__ __forceinline__ void cp_commit() {
    asm volatile("cp.async.commit_group;");
}
__device__ __forceinline__ void cp_wait0() {
    asm volatile("cp.async.wait_group 0;");
}
__device__ __forceinline__ uint32_t packbf(float a, float b) {
    __nv_bfloat162 h = __float22bfloat162_rn(make_float2(a, b));
    return *(uint32_t*)&h;
}
__device__ __forceinline__ uint32_t hadd2u(uint32_t a, uint32_t b) {
    __nv_bfloat162 r = __hadd2(*(__nv_bfloat162*)&a, *(__nv_bfloat162*)&b);
    return *(uint32_t*)&r;
}

// ---------------- fp32 -> bf16 conversion (all tensors, one kernel) -------------
__global__ void convert_all(const float* __restrict__ h, const float* __restrict__ p,
                            const float* __restrict__ qw, const float* __restrict__ kvw,
                            const float* __restrict__ rw, const float* __restrict__ wo)
{
    const int N1 = 786432;            // hidden  (float4 units)
    const int N2 = N1 + 1572864;      // pos_emb
    const int N3 = N2 + 147456;       // qw
    const int N4 = N3 + 147456;       // kvw
    const int N5 = N4 + 147456;       // rw
    const int N6 = N5 + 147456;       // wo
    for (int i = blockIdx.x * blockDim.x + threadIdx.x; i < N6;
         i += gridDim.x * blockDim.x) {
        const float* src; __nv_bfloat16* dst; int li;
        if      (i < N1) { src = h;   dst = g_hidb; li = i; }
        else if (i < N2) { src = p;   dst = g_posb; li = i - N1; }
        else if (i < N3) { src = qw;  dst = g_qwb;  li = i - N2; }
        else if (i < N4) { src = kvw; dst = g_kvwb; li = i - N3; }
        else if (i < N5) { src = rw;  dst = g_rwgt; li = i - N4; }
        else             { src = wo;  dst = g_wob;  li = i - N5; }
        float4 v = ((const float4*)src)[li];
        uint2 u;
        u.x = packbf(v.x, v.y);
        u.y = packbf(v.z, v.w);
        ((uint2*)dst)[li] = u;
    }
}

// ---------------- bf16 GEMM, cp.async double-buffered 128x128x64 ----------------
#define GAST 9216   // A stage halves (128*72)
#define GBST 8704   // B stage halves (64*136)
__device__ __forceinline__ void gemm_load(int tid, const __nv_bfloat16* A,
    const __nv_bfloat16* Bm, int K, int N, int m0, int n0, int k0,
    uint32_t abase, uint32_t bbase)
{
#pragma unroll
    for (int it = 0; it < 4; it++) {
        const int id = tid + it * 256;
        const int r = id >> 3, c = (id & 7) * 8;
        cpa16(abase + (r * 72 + c) * 2, &A[(size_t)(m0 + r) * K + k0 + c]);
    }
#pragma unroll
    for (int it = 0; it < 4; it++) {
        const int id = tid + it * 256;
        const int r = id >> 4, c = (id & 15) * 8;
        cpa16(bbase + (r * 136 + c) * 2, &Bm[(size_t)(k0 + r) * N + n0 + c]);
    }
    cp_commit();
}

template<typename TC, bool EPI>
__global__ __launch_bounds__(256) void gemm_bf16(
    const __nv_bfloat16* __restrict__ A, const __nv_bfloat16* __restrict__ Bm,
    TC* __restrict__ C, int M, int N, int K,
    const float* __restrict__ bias, const float* __restrict__ resid)
{
    extern __shared__ __align__(16) __nv_bfloat16 gsm[];
    __nv_bfloat16* As = gsm;               // 2 stages of 128x72
    __nv_bfloat16* Bs = gsm + 2 * GAST;    // 2 stages of 64x136
    const int tid = threadIdx.x;
    const int m0 = blockIdx.y * 128, n0 = blockIdx.x * 128;
    const int wid = tid >> 5, lane = tid & 31;
    const int wm = wid & 1, wn = wid >> 1;
    const int g = lane >> 2, tig = lane & 3;

    const uint32_t asm0 = sptr(As), bsm0 = sptr(Bs);
    gemm_load(tid, A, Bm, K, N, m0, n0, 0, asm0, bsm0);

    float acc[4][4][4];
#pragma unroll
    for (int mi = 0; mi < 4; mi++)
#pragma unroll
        for (int nt = 0; nt < 4; nt++)
#pragma unroll
            for (int e = 0; e < 4; e++) acc[mi][nt][e] = 0.f;

    const uint32_t a_base = asm0 + (((wm * 64 + (lane & 15)) * 72 + (lane >> 4) * 8) << 1);
    const uint32_t b_base = bsm0 + ((((lane & 15)) * 136 + wn * 32 + (lane >> 4) * 8) << 1);

    const int KI = K >> 6;
    for (int ki = 0; ki < KI; ki++) {
        cp_wait0();
        __syncthreads();
        if (ki + 1 < KI)
            gemm_load(tid, A, Bm, K, N, m0, n0, (ki + 1) * 64,
                      asm0 + (((ki + 1) & 1) * GAST << 1),
                      bsm0 + (((ki + 1) & 1) * GBST << 1));
        const uint32_t ao = ((ki & 1) * GAST) << 1;
        const uint32_t bo = ((ki & 1) * GBST) << 1;
#pragma unroll
        for (int kc = 0; kc < 4; kc++) {
            uint32_t af[4][4], bv[2][4];
#pragma unroll
            for (int mi = 0; mi < 4; mi++)
                ldsm4(af[mi], a_base + ao + ((mi * 16 * 72 + kc * 16) << 1));
#pragma unroll
            for (int nn = 0; nn < 2; nn++)
                ldsm4t(bv[nn], b_base + bo + ((kc * 16 * 136 + nn * 16) << 1));
#pragma unroll
            for (int mi = 0; mi < 4; mi++)
#pragma unroll
                for (int nn = 0; nn < 2; nn++) {
                    mma16816(acc[mi][2 * nn + 0], af[mi], &bv[nn][0]);
                    mma16816(acc[mi][2 * nn + 1], af[mi], &bv[nn][2]);
                }
        }
        __syncthreads();
    }

#pragma unroll
    for (int mi = 0; mi < 4; mi++) {
#pragma unroll
        for (int nt = 0; nt < 4; nt++) {
            const int col = n0 + wn * 32 + nt * 8 + 2 * tig;
#pragma unroll
            for (int half = 0; half < 2; half++) {
                const int r = m0 + wm * 64 + mi * 16 + g + half * 8;
                float v0 = acc[mi][nt][half * 2 + 0];
                float v1 = acc[mi][nt][half * 2 + 1];
                if (EPI) {
                    float x0 = v0 + bias[col]     + resid[(size_t)r * N + col];
                    float x1 = v1 + bias[col + 1] + resid[(size_t)r * N + col + 1];
                    v0 = 0.5f * x0 * (1.f + erff(x0 * 0.70710678118654752f));
                    v1 = 0.5f * x1 * (1.f + erff(x1 * 0.70710678118654752f));
                    float* cp = (float*)&C[(size_t)r * N + col];
                    cp[0] = v0; cp[1] = v1;
                } else {
                    *(uint32_t*)&C[(size_t)r * N + col] = packbf(v0, v1);
                }
            }
        }
    }
}

// ---------------- FA2-style flash attention, kr ring + delta-fragments ----------
// 128 query rows per block, 8 warps x 16 rows. kr kept in a 256-row ring buffer
// (ldmatrix per-lane addresses handle the mod-256 wrap); only 64 new rows loaded
// per key tile. Qr fragments = Qw fragments + packed bf16 (r_r_bias - r_w_bias).
#define FLH 72
#define FGS 68
__global__ __launch_bounds__(256, 2) void flash_mma(const float* __restrict__ mask,
    const float* __restrict__ rwbias, const float* __restrict__ rrbias)
{
    extern __shared__ __align__(16) char smraw[];
    __nv_bfloat16* qw_s = (__nv_bfloat16*)smraw;        // 128 x 72
    __nv_bfloat16* kv_s = qw_s + 128 * FLH;             // 2 x 64 x 72
    __nv_bfloat16* kr_s = kv_s + 2 * 64 * FLH;          // ring: 256 x 72
    float* gsh = (float*)(kr_s + 256 * FLH);            // 8 x 16 x 68
    float* bw  = gsh + 8 * 16 * FGS;                    // 64
    float* br  = bw + 64;                               // 64

    const int b = blockIdx.z, n = blockIdx.y;
    const int i0 = blockIdx.x * 128;
    const int tid = threadIdx.x;
    const int w = tid >> 5, lane = tid & 31;
    const int g = lane >> 2, tig = lane & 3;
    const int pb0 = 897 - i0;   // absolute kr row of window start at jt=0

    if (tid < 64)       bw[tid]      = rwbias[n * DH_ + tid];
    else if (tid < 128) br[tid - 64] = rrbias[n * DH_ + tid - 64];
    __syncthreads();

    const uint32_t kvsm = sptr(kv_s), krsm = sptr(kr_s);

    // ---- initial async loads: kv tile 0 + full 191-row kr window ----
#pragma unroll
    for (int it = 0; it < 2; it++) {
        const int id = tid + it * 256;
        const int r = id >> 3, c = (id & 7) * 8;
        cpa16(kvsm + (r * FLH + c) * 2,
              &g_kvh[(((size_t)b * S_ + r) * NH_ + n) * DH_ + c]);
    }
#pragma unroll
    for (int it = 0; it < 6; it++) {
        const int id = tid + it * 256;
        const int r = id >> 3, c = (id & 7) * 8;
        if (r < 191) {
            const int rowabs = pb0 + r;
            cpa16(krsm + ((rowabs & 255) * FLH + c) * 2,
                  &g_kr[(((size_t)b * POS_ + rowabs) * NH_ + n) * DH_ + c]);
        }
    }
    cp_commit();

    // ---- build biased Q tile (q + r_w_bias) ----
#pragma unroll
    for (int it = 0; it < 4; it++) {
        const int id = tid + it * 256;
        const int r = id >> 3, c = (id & 7) * 8;
        uint4 v = *(const uint4*)&g_qh[(((size_t)b * S_ + i0 + r) * NH_ + n) * DH_ + c];
        __nv_bfloat162* hp = (__nv_bfloat162*)&v;
        uint4 ow;
        uint32_t* wp = (uint32_t*)&ow;
#pragma unroll
        for (int k = 0; k < 4; k++) {
            float2 f = __bfloat1622float2(hp[k]);
            wp[k] = packbf(f.x + bw[c + 2 * k], f.y + bw[c + 2 * k + 1]);
        }
        *(uint4*)&qw_s[r * FLH + c] = ow;
    }

    // ---- delta fragments: packed bf16 (br - bw) at this lane's A-frag k slots ----
    uint32_t dpk0[4], dpk1[4];
#pragma unroll
    for (int kc = 0; kc < 4; kc++) {
        const int kA = 16 * kc + 2 * tig;
        dpk0[kc] = packbf(br[kA] - bw[kA], br[kA + 1] - bw[kA + 1]);
        dpk1[kc] = packbf(br[kA + 8] - bw[kA + 8], br[kA + 9] - bw[kA + 9]);
    }
    __syncthreads();

    const uint32_t qwa = sptr(qw_s) + (((16 * w + (lane & 15)) * FLH + (lane >> 4) * 8) << 1);
    const uint32_t kvn = kvsm + (((((lane >> 4) * 8 + (lane & 7)) * FLH) + ((lane >> 3) & 1) * 8) << 1);
    const uint32_t kvt = kvsm + ((((lane & 15)) * FLH + (lane >> 4) * 8) << 1);
    const int laneRow = (lane >> 4) * 8 + (lane & 7);      // kr B-frag row
    const int khalf   = ((lane >> 3) & 1) * 8;             // kr B-frag k half

    float m0v = -1e30f, m1v = -1e30f, l0v = 0.f, l1v = 0.f;
    float acc_o[8][4];
#pragma unroll
    for (int nt = 0; nt < 8; nt++)
#pragma unroll
        for (int e = 0; e < 4; e++) acc_o[nt][e] = 0.f;

    const int nt0 = 14 - 2 * w;
    float* gw = gsh + w * 16 * FGS;
    const int gi0 = i0 + 16 * w + g;
    const float* mrow0 = mask + ((size_t)b * S_ + gi0) * S_;
    const float* mrow1 = mrow0 + 8 * S_;

    for (int jt = 0; jt < 16; jt++) {
        cp_wait0();
        __syncthreads();
        if (jt < 15) {
            // prefetch kv(jt+1) + 64 new kr ring rows
            const int j1 = (jt + 1) * 64;
            const uint32_t kvb = kvsm + (((jt + 1) & 1) * 64 * FLH << 1);
#pragma unroll
            for (int it = 0; it < 2; it++) {
                const int id = tid + it * 256;
                const int r = id >> 3, c = (id & 7) * 8;
                cpa16(kvb + (r * FLH + c) * 2,
                      &g_kvh[(((size_t)b * S_ + j1 + r) * NH_ + n) * DH_ + c]);
            }
            const int nb = pb0 + 64 * jt + 191;
#pragma unroll
            for (int it = 0; it < 2; it++) {
                const int id = tid + it * 256;
                const int r = id >> 3, c = (id & 7) * 8;
                const int rowabs = nb + r;
                cpa16(krsm + ((rowabs & 255) * FLH + c) * 2,
                      &g_kr[(((size_t)b * POS_ + rowabs) * NH_ + n) * DH_ + c]);
            }
            cp_commit();
        }
        const uint32_t kvo = ((jt & 1) * 64 * FLH) << 1;
        const int j0 = jt * 64;
        const int rowj = pb0 + 64 * jt + laneRow;

        // ---- S = Qw @ KV^T (keep A-fragments for the G pass) ----
        float acc_s[8][4];
#pragma unroll
        for (int nt = 0; nt < 8; nt++)
#pragma unroll
            for (int e = 0; e < 4; e++) acc_s[nt][e] = 0.f;
        uint32_t af[4][4];
#pragma unroll
        for (int kc = 0; kc < 4; kc++) {
            ldsm4(af[kc], qwa + kc * 32);
#pragma unroll
            for (int nn = 0; nn < 4; nn++) {
                uint32_t bf[4];
                ldsm4(bf, kvn + kvo + (((nn * 16) * FLH + kc * 16) << 1));
                mma16816(acc_s[2 * nn + 0], af[kc], &bf[0]);
                mma16816(acc_s[2 * nn + 1], af[kc], &bf[2]);
            }
        }

        // ---- banded G = Qr @ KR_ring^T, scatter pre-shifted ----
        __syncwarp();
#pragma unroll
        for (int np = 0; np < 5; np++) {
            const int tr = (nt0 + 2 * np) * 8;
            const uint32_t kra = krsm + ((((rowj + tr) & 255) * FLH + khalf) << 1);
            float ga[4] = {0.f, 0.f, 0.f, 0.f};
            float gb[4] = {0.f, 0.f, 0.f, 0.f};
#pragma unroll
            for (int kc = 0; kc < 4; kc++) {
                uint32_t bf[4];
                ldsm4(bf, kra + kc * 32);
                uint32_t afr[4] = { hadd2u(af[kc][0], dpk0[kc]),
                                    hadd2u(af[kc][1], dpk0[kc]),
                                    hadd2u(af[kc][2], dpk1[kc]),
                                    hadd2u(af[kc][3], dpk1[kc]) };
                mma16816(ga, afr, &bf[0]);
                mma16816(gb, afr, &bf[2]);
            }
            const int base = tr + 2 * tig + 16 * w - 127;
            const int cA = base + g;
            const int cB = cA + 8;
            if ((unsigned)cA < 64u)        gw[g * FGS + cA]             = ga[0];
            if ((unsigned)(cA + 1) < 64u)  gw[g * FGS + cA + 1]         = ga[1];
            if ((unsigned)cB < 64u)        gw[(g + 8) * FGS + cB]       = ga[2];
            if ((unsigned)(cB + 1) < 64u)  gw[(g + 8) * FGS + cB + 1]   = ga[3];
            const int cA2 = cA + 8;
            const int cB2 = cB + 8;
            if ((unsigned)cA2 < 64u)       gw[g * FGS + cA2]            = gb[0];
            if ((unsigned)(cA2 + 1) < 64u) gw[g * FGS + cA2 + 1]        = gb[1];
            if ((unsigned)cB2 < 64u)       gw[(g + 8) * FGS + cB2]      = gb[2];
            if ((unsigned)(cB2 + 1) < 64u) gw[(g + 8) * FGS + cB2 + 1]  = gb[3];
        }
        __syncwarp();

        // ---- add G, mask, scale; online softmax in registers ----
        float rmax0 = -1e30f, rmax1 = -1e30f;
#pragma unroll
        for (int nt = 0; nt < 8; nt++) {
#pragma unroll
            for (int e = 0; e < 2; e++) {
                const int col = nt * 8 + 2 * tig + e;
                float v0 = (acc_s[nt][e]     + gw[g * FGS + col])       * 0.125f
                           + mrow0[j0 + col] * (-65500.0f);
                float v1 = (acc_s[nt][2 + e] + gw[(g + 8) * FGS + col]) * 0.125f
                           + mrow1[j0 + col] * (-65500.0f);
                acc_s[nt][e] = v0; acc_s[nt][2 + e] = v1;
                rmax0 = fmaxf(rmax0, v0); rmax1 = fmaxf(rmax1, v1);
            }
        }
        rmax0 = fmaxf(rmax0, __shfl_xor_sync(0xffffffffu, rmax0, 1));
        rmax0 = fmaxf(rmax0, __shfl_xor_sync(0xffffffffu, rmax0, 2));
        rmax1 = fmaxf(rmax1, __shfl_xor_sync(0xffffffffu, rmax1, 1));
        rmax1 = fmaxf(rmax1, __shfl_xor_sync(0xffffffffu, rmax1, 2));
        const float mn0 = fmaxf(m0v, rmax0), mn1 = fmaxf(m1v, rmax1);
        const float cr0 = __expf(m0v - mn0), cr1 = __expf(m1v - mn1);
        m0v = mn0; m1v = mn1;
        float ls0 = 0.f, ls1 = 0.f;
#pragma unroll
        for (int nt = 0; nt < 8; nt++) {
#pragma unroll
            for (int e = 0; e < 2; e++) {
                const float p0 = __expf(acc_s[nt][e] - mn0);
                const float p1 = __expf(acc_s[nt][2 + e] - mn1);
                ls0 += p0; ls1 += p1;
                acc_s[nt][e] = p0; acc_s[nt][2 + e] = p1;
            }
        }
        ls0 += __shfl_xor_sync(0xffffffffu, ls0, 1);
        ls0 += __shfl_xor_sync(0xffffffffu, ls0, 2);
        ls1 += __shfl_xor_sync(0xffffffffu, ls1, 1);
        ls1 += __shfl_xor_sync(0xffffffffu, ls1, 2);
        l0v = l0v * cr0 + ls0;
        l1v = l1v * cr1 + ls1;

        // rescale O; pack P fragments (register repack, no smem)
        uint32_t pa[4][4];
#pragma unroll
        for (int kc = 0; kc < 4; kc++) {
            pa[kc][0] = packbf(acc_s[2 * kc][0],     acc_s[2 * kc][1]);
            pa[kc][1] = packbf(acc_s[2 * kc][2],     acc_s[2 * kc][3]);
            pa[kc][2] = packbf(acc_s[2 * kc + 1][0], acc_s[2 * kc + 1][1]);
            pa[kc][3] = packbf(acc_s[2 * kc + 1][2], acc_s[2 * kc + 1][3]);
        }
#pragma unroll
        for (int nt = 0; nt < 8; nt++) {
            acc_o[nt][0] *= cr0; acc_o[nt][1] *= cr0;
            acc_o[nt][2] *= cr1; acc_o[nt][3] *= cr1;
        }

        // ---- O += P @ V ----
#pragma unroll
        for (int kc = 0; kc < 4; kc++) {
#pragma unroll
            for (int nn = 0; nn < 4; nn++) {
                uint32_t bf[4];
                ldsm4t(bf, kvt + kvo + (((kc * 16) * FLH + nn * 16) << 1));
                mma16816(acc_o[2 * nn + 0], pa[kc], &bf[0]);
                mma16816(acc_o[2 * nn + 1], pa[kc], &bf[2]);
            }
        }
    }

    // ---- normalize and store (bf16 ctx) ----
    const float inv0 = 1.f / l0v, inv1 = 1.f / l1v;
    const size_t b0 = (((size_t)b * S_ + i0 + 16 * w + g) * NH_ + n) * (size_t)DH_;
    const size_t b1 = b0 + 8 * (size_t)NH_ * DH_;
#pragma unroll
    for (int nt = 0; nt < 8; nt++) {
        const int c = nt * 8 + 2 * tig;
        *(uint32_t*)&g_ctx[b0 + c] = packbf(acc_o[nt][0] * inv0, acc_o[nt][1] * inv0);
        *(uint32_t*)&g_ctx[b1 + c] = packbf(acc_o[nt][2] * inv1, acc_o[nt][3] * inv1);
    }
}

// -------------------------------- launch ---------------------------------------
extern "C" void kernel_launch(void* const* d_in, const int* in_sizes, int n_in,
                              void* d_out, int out_size)
{
    const float* hidden   = (const float*)d_in[0];
    const float* pos_emb  = (const float*)d_in[1];
    const float* mask     = (const float*)d_in[2];
    const float* qw       = (const float*)d_in[3];
    const float* kvw      = (const float*)d_in[4];
    const float* rw       = (const float*)d_in[5];
    const float* r_r_bias = (const float*)d_in[6];
    const float* r_w_bias = (const float*)d_in[7];
    const float* w_out    = (const float*)d_in[8];
    const float* b_out    = (const float*)d_in[9];
    float* out = (float*)d_out;

    __nv_bfloat16 *hidb, *posb, *qwb, *kvwb, *rwgt, *wob, *qh, *kvh, *kr, *ctx;
    cudaGetSymbolAddress((void**)&hidb, g_hidb);
    cudaGetSymbolAddress((void**)&posb, g_posb);
    cudaGetSymbolAddress((void**)&qwb,  g_qwb);
    cudaGetSymbolAddress((void**)&kvwb, g_kvwb);
    cudaGetSymbolAddress((void**)&rwgt, g_rwgt);
    cudaGetSymbolAddress((void**)&wob,  g_wob);
    cudaGetSymbolAddress((void**)&qh,   g_qh);
    cudaGetSymbolAddress((void**)&kvh,  g_kvh);
    cudaGetSymbolAddress((void**)&kr,   g_kr);
    cudaGetSymbolAddress((void**)&ctx,  g_ctx);

    const int gemm_smem  = (2 * GAST + 2 * GBST) * 2;           // 71680 B
    const int flash_smem = (128 * FLH + 2 * 64 * FLH + 256 * FLH) * 2
                           + (8 * 16 * FGS + 128) * 4;          // 109056 B
    cudaFuncSetAttribute(gemm_bf16<__nv_bfloat16, false>,
                         cudaFuncAttributeMaxDynamicSharedMemorySize, gemm_smem);
    cudaFuncSetAttribute(gemm_bf16<float, true>,
                         cudaFuncAttributeMaxDynamicSharedMemorySize, gemm_smem);
    cudaFuncSetAttribute(flash_mma,
                         cudaFuncAttributeMaxDynamicSharedMemorySize, flash_smem);

    // fp32 -> bf16 conversion of all GEMM inputs
    convert_all<<<2048, 256>>>(hidden, pos_emb, qw, kvw, rw, w_out);

    // projections (bf16, cp.async pipelined)
    gemm_bf16<__nv_bfloat16, false><<<dim3(6, 32), 256, gemm_smem>>>(
        hidb, qwb,  qh,  B_*S_,   H_, H_, nullptr, nullptr);
    gemm_bf16<__nv_bfloat16, false><<<dim3(6, 32), 256, gemm_smem>>>(
        hidb, kvwb, kvh, B_*S_,   H_, H_, nullptr, nullptr);
    gemm_bf16<__nv_bfloat16, false><<<dim3(6, 64), 256, gemm_smem>>>(
        posb, rwgt, kr,  B_*POS_, H_, H_, nullptr, nullptr);

    // fused attention (kr ring buffer, delta-fragment Qr, banded rel_shift)
    flash_mma<<<dim3(S_/128, NH_, B_), 256, flash_smem>>>(mask, r_w_bias, r_r_bias);

    // output projection + bias + residual + exact GELU
    gemm_bf16<float, true><<<dim3(6, 32), 256, gemm_smem>>>(
        ctx, wob, out, B_*S_, H_, H_, b_out, hidden);
}

// round 6
// speedup vs baseline: 6.3102x; 1.1001x over previous
#include <cuda_runtime.h>
#include <cuda_bf16.h>
#include <math.h>
#include <stdint.h>

#define B_   4
#define S_   1024
#define H_   768
#define NH_  12
#define DH_  64
#define POS_ 2048

// ---------------- scratch (static device arrays; no allocations) ----------------
__device__ __nv_bfloat16 g_hidb[B_*S_*H_];
__device__ __nv_bfloat16 g_posb[B_*POS_*H_];
__device__ __nv_bfloat16 g_qwb [H_*H_];
__device__ __nv_bfloat16 g_kvwb[H_*H_];
__device__ __nv_bfloat16 g_rwgt[H_*H_];
__device__ __nv_bfloat16 g_wob [H_*H_];
__device__ __nv_bfloat16 g_qh [B_*S_*H_];
__device__ __nv_bfloat16 g_kvh[B_*S_*H_];
__device__ __nv_bfloat16 g_kr [B_*POS_*H_];
__device__ __nv_bfloat16 g_ctx[B_*S_*H_];

// ---------------- PTX helpers ---------------------------------------------------
__device__ __forceinline__ uint32_t sptr(const void* p) {
    return (uint32_t)__cvta_generic_to_shared(p);
}
__device__ __forceinline__ void ldsm4(uint32_t* r, uint32_t a) {
    asm volatile("ldmatrix.sync.aligned.m8n8.x4.shared.b16 {%0,%1,%2,%3},[%4];"
                 : "=r"(r[0]), "=r"(r[1]), "=r"(r[2]), "=r"(r[3]) : "r"(a));
}
__device__ __forceinline__ void ldsm4t(uint32_t* r, uint32_t a) {
    asm volatile("ldmatrix.sync.aligned.m8n8.x4.trans.shared.b16 {%0,%1,%2,%3},[%4];"
                 : "=r"(r[0]), "=r"(r[1]), "=r"(r[2]), "=r"(r[3]) : "r"(a));
}
__device__ __forceinline__ void mma16816(float* d, const uint32_t* a, const uint32_t* b) {
    asm volatile(
        "mma.sync.aligned.m16n8k16.row.col.f32.bf16.bf16.f32 "
        "{%0,%1,%2,%3},{%4,%5,%6,%7},{%8,%9},{%0,%1,%2,%3};"
        : "+f"(d[0]), "+f"(d[1]), "+f"(d[2]), "+f"(d[3])
        : "r"(a[0]), "r"(a[1]), "r"(a[2]), "r"(a[3]), "r"(b[0]), "r"(b[1]));
}
__device__ __forceinline__ void cpa16(uint32_t dst, const void* src) {
    asm volatile("cp.async.cg.shared.global [%0], [%1], 16;" :: "r"(dst), "l"(src));
}
__device__ __forceinline__ void cp_commit() {
    asm volatile("cp.async.commit_group;");
}
__device__ __forceinline__ void cp_wait0() {
    asm volatile("cp.async.wait_group 0;");
}
__device__ __forceinline__ void cp_wait1() {
    asm volatile("cp.async.wait_group 1;");
}
__device__ __forceinline__ uint32_t packbf(float a, float b) {
    __nv_bfloat162 h = __float22bfloat162_rn(make_float2(a, b));
    return *(uint32_t*)&h;
}
__device__ __forceinline__ uint32_t hadd2u(uint32_t a, uint32_t b) {
    __nv_bfloat162 r = __hadd2(*(__nv_bfloat162*)&a, *(__nv_bfloat162*)&b);
    return *(uint32_t*)&r;
}

// ---------------- fp32 -> bf16 conversion (all tensors, one kernel) -------------
__global__ void convert_all(const float* __restrict__ h, const float* __restrict__ p,
                            const float* __restrict__ qw, const float* __restrict__ kvw,
                            const float* __restrict__ rw, const float* __restrict__ wo)
{
    const int N1 = 786432;            // hidden  (float4 units)
    const int N2 = N1 + 1572864;      // pos_emb
    const int N3 = N2 + 147456;       // qw
    const int N4 = N3 + 147456;       // kvw
    const int N5 = N4 + 147456;       // rw
    const int N6 = N5 + 147456;       // wo
    for (int i = blockIdx.x * blockDim.x + threadIdx.x; i < N6;
         i += gridDim.x * blockDim.x) {
        const float* src; __nv_bfloat16* dst; int li;
        if      (i < N1) { src = h;   dst = g_hidb; li = i; }
        else if (i < N2) { src = p;   dst = g_posb; li = i - N1; }
        else if (i < N3) { src = qw;  dst = g_qwb;  li = i - N2; }
        else if (i < N4) { src = kvw; dst = g_kvwb; li = i - N3; }
        else if (i < N5) { src = rw;  dst = g_rwgt; li = i - N4; }
        else             { src = wo;  dst = g_wob;  li = i - N5; }
        float4 v = ((const float4*)src)[li];
        uint2 u;
        u.x = packbf(v.x, v.y);
        u.y = packbf(v.z, v.w);
        ((uint2*)dst)[li] = u;
    }
}

// ---------------- 3-stage bf16 GEMM core, 128x128x64 tiles, K=N=768 -------------
// Stage layout: A tile 128x72 halves (9216), then W tile 64x136 halves (8704).
#define PSTG 17920      // halves per stage
#define NKI  12         // 768 / 64

__device__ __forceinline__ void pj_load(int tid, const __nv_bfloat16* A,
    const __nv_bfloat16* W, int m0, int c0, int k0, uint32_t sbase)
{
#pragma unroll
    for (int it = 0; it < 4; it++) {
        const int id = tid + it * 256;
        const int r = id >> 3, c = (id & 7) * 8;
        cpa16(sbase + (r * 72 + c) * 2, &A[(size_t)(m0 + r) * H_ + k0 + c]);
    }
#pragma unroll
    for (int it = 0; it < 4; it++) {
        const int id = tid + it * 256;
        const int r = id >> 4, c = (id & 15) * 8;
        cpa16(sbase + (9216 + r * 136 + c) * 2, &W[(size_t)(k0 + r) * H_ + c0 + c]);
    }
    cp_commit();
}

template<bool EPI>
__device__ __forceinline__ void gemm3_body(
    const __nv_bfloat16* __restrict__ A, const __nv_bfloat16* __restrict__ W,
    int m0, int c0, __nv_bfloat16* __restrict__ outH, float* __restrict__ outF,
    const float* __restrict__ bias, const float* __restrict__ resid)
{
    extern __shared__ __align__(16) __nv_bfloat16 gsm[];
    const int tid = threadIdx.x;
    const int wid = tid >> 5, lane = tid & 31;
    const int wm = wid & 1, wn = wid >> 1;
    const int g = lane >> 2, tig = lane & 3;

    const uint32_t s0 = sptr(gsm);
    pj_load(tid, A, W, m0, c0, 0,  s0);
    pj_load(tid, A, W, m0, c0, 64, s0 + (PSTG << 1));

    float acc[4][4][4];
#pragma unroll
    for (int mi = 0; mi < 4; mi++)
#pragma unroll
        for (int nt = 0; nt < 4; nt++)
#pragma unroll
            for (int e = 0; e < 4; e++) acc[mi][nt][e] = 0.f;

    const uint32_t a_off = ((wm * 64 + (lane & 15)) * 72 + (lane >> 4) * 8) << 1;
    const uint32_t b_off = (9216 + ((lane & 15)) * 136 + wn * 32 + (lane >> 4) * 8) << 1;

    for (int ki = 0; ki < NKI; ki++) {
        if (ki == NKI - 1) cp_wait0(); else cp_wait1();
        __syncthreads();
        if (ki + 2 < NKI)
            pj_load(tid, A, W, m0, c0, (ki + 2) * 64,
                    s0 + (((ki + 2) % 3) * PSTG << 1));
        const uint32_t sb = s0 + ((ki % 3) * PSTG << 1);
        const uint32_t a_base = sb + a_off, b_base = sb + b_off;
#pragma unroll
        for (int kc = 0; kc < 4; kc++) {
            uint32_t af[4][4], bv[2][4];
#pragma unroll
            for (int mi = 0; mi < 4; mi++)
                ldsm4(af[mi], a_base + ((mi * 16 * 72 + kc * 16) << 1));
#pragma unroll
            for (int nn = 0; nn < 2; nn++)
                ldsm4t(bv[nn], b_base + ((kc * 16 * 136 + nn * 16) << 1));
#pragma unroll
            for (int mi = 0; mi < 4; mi++)
#pragma unroll
                for (int nn = 0; nn < 2; nn++) {
                    mma16816(acc[mi][2 * nn + 0], af[mi], &bv[nn][0]);
                    mma16816(acc[mi][2 * nn + 1], af[mi], &bv[nn][2]);
                }
        }
    }

#pragma unroll
    for (int mi = 0; mi < 4; mi++) {
#pragma unroll
        for (int nt = 0; nt < 4; nt++) {
            const int col = c0 + wn * 32 + nt * 8 + 2 * tig;
#pragma unroll
            for (int half = 0; half < 2; half++) {
                const int r = m0 + wm * 64 + mi * 16 + g + half * 8;
                float v0 = acc[mi][nt][half * 2 + 0];
                float v1 = acc[mi][nt][half * 2 + 1];
                if (EPI) {
                    float x0 = v0 + bias[col]     + resid[(size_t)r * H_ + col];
                    float x1 = v1 + bias[col + 1] + resid[(size_t)r * H_ + col + 1];
                    v0 = 0.5f * x0 * (1.f + erff(x0 * 0.70710678118654752f));
                    v1 = 0.5f * x1 * (1.f + erff(x1 * 0.70710678118654752f));
                    float* cp = &outF[(size_t)r * H_ + col];
                    cp[0] = v0; cp[1] = v1;
                } else {
                    *(uint32_t*)&outH[(size_t)r * H_ + col] = packbf(v0, v1);
                }
            }
        }
    }
}

// All three projections in ONE launch: 768 blocks.
// bid < 384: qkv (A=hidb, M=4096): x=bid%12 (x<6 -> q, else kv), y=bid/12
// bid >= 384: r  (A=posb, M=8192): x=t%6, y=t/6
__global__ __launch_bounds__(256, 2) void proj_all()
{
    const int bid = blockIdx.x;
    const __nv_bfloat16 *A, *W;
    __nv_bfloat16* C;
    int m0, c0;
    if (bid < 384) {
        const int x = bid % 12, y = bid / 12;
        m0 = y * 128;
        A = g_hidb;
        if (x < 6) { W = g_qwb;  C = g_qh;  c0 = x * 128; }
        else       { W = g_kvwb; C = g_kvh; c0 = (x - 6) * 128; }
    } else {
        const int t = bid - 384;
        const int x = t % 6, y = t / 6;
        m0 = y * 128; c0 = x * 128;
        A = g_posb; W = g_rwgt; C = g_kr;
    }
    gemm3_body<false>(A, W, m0, c0, C, nullptr, nullptr, nullptr);
}

// Output projection + bias + residual + exact GELU. 192 blocks (6 x 32).
__global__ __launch_bounds__(256, 2) void gemm_epi(
    float* __restrict__ out, const float* __restrict__ bias,
    const float* __restrict__ resid)
{
    const int x = blockIdx.x % 6, y = blockIdx.x / 6;
    gemm3_body<true>(g_ctx, g_wob, y * 128, x * 128, nullptr, out, bias, resid);
}

// ---------------- FA2-style flash attention, kr ring + delta-fragments ----------
#define FLH 72
#define FGS 68
__global__ __launch_bounds__(256, 2) void flash_mma(const float* __restrict__ mask,
    const float* __restrict__ rwbias, const float* __restrict__ rrbias)
{
    extern __shared__ __align__(16) char smraw[];
    __nv_bfloat16* qw_s = (__nv_bfloat16*)smraw;        // 128 x 72
    __nv_bfloat16* kv_s = qw_s + 128 * FLH;             // 2 x 64 x 72
    __nv_bfloat16* kr_s = kv_s + 2 * 64 * FLH;          // ring: 256 x 72
    float* gsh = (float*)(kr_s + 256 * FLH);            // 8 x 16 x 68
    float* bw  = gsh + 8 * 16 * FGS;                    // 64
    float* br  = bw + 64;                               // 64

    const int b = blockIdx.z, n = blockIdx.y;
    const int i0 = blockIdx.x * 128;
    const int tid = threadIdx.x;
    const int w = tid >> 5, lane = tid & 31;
    const int g = lane >> 2, tig = lane & 3;
    const int pb0 = 897 - i0;   // absolute kr row of window start at jt=0

    if (tid < 64)       bw[tid]      = rwbias[n * DH_ + tid];
    else if (tid < 128) br[tid - 64] = rrbias[n * DH_ + tid - 64];
    __syncthreads();

    const uint32_t kvsm = sptr(kv_s), krsm = sptr(kr_s);

    // ---- initial async loads: kv tile 0 + full 191-row kr window ----
#pragma unroll
    for (int it = 0; it < 2; it++) {
        const int id = tid + it * 256;
        const int r = id >> 3, c = (id & 7) * 8;
        cpa16(kvsm + (r * FLH + c) * 2,
              &g_kvh[(((size_t)b * S_ + r) * NH_ + n) * DH_ + c]);
    }
#pragma unroll
    for (int it = 0; it < 6; it++) {
        const int id = tid + it * 256;
        const int r = id >> 3, c = (id & 7) * 8;
        if (r < 191) {
            const int rowabs = pb0 + r;
            cpa16(krsm + ((rowabs & 255) * FLH + c) * 2,
                  &g_kr[(((size_t)b * POS_ + rowabs) * NH_ + n) * DH_ + c]);
        }
    }
    cp_commit();

    // ---- build biased Q tile (q + r_w_bias) ----
#pragma unroll
    for (int it = 0; it < 4; it++) {
        const int id = tid + it * 256;
        const int r = id >> 3, c = (id & 7) * 8;
        uint4 v = *(const uint4*)&g_qh[(((size_t)b * S_ + i0 + r) * NH_ + n) * DH_ + c];
        __nv_bfloat162* hp = (__nv_bfloat162*)&v;
        uint4 ow;
        uint32_t* wp = (uint32_t*)&ow;
#pragma unroll
        for (int k = 0; k < 4; k++) {
            float2 f = __bfloat1622float2(hp[k]);
            wp[k] = packbf(f.x + bw[c + 2 * k], f.y + bw[c + 2 * k + 1]);
        }
        *(uint4*)&qw_s[r * FLH + c] = ow;
    }

    // ---- delta fragments: packed bf16 (br - bw) at this lane's A-frag k slots ----
    uint32_t dpk0[4], dpk1[4];
#pragma unroll
    for (int kc = 0; kc < 4; kc++) {
        const int kA = 16 * kc + 2 * tig;
        dpk0[kc] = packbf(br[kA] - bw[kA], br[kA + 1] - bw[kA + 1]);
        dpk1[kc] = packbf(br[kA + 8] - bw[kA + 8], br[kA + 9] - bw[kA + 9]);
    }
    __syncthreads();

    const uint32_t qwa = sptr(qw_s) + (((16 * w + (lane & 15)) * FLH + (lane >> 4) * 8) << 1);
    const uint32_t kvn = kvsm + (((((lane >> 4) * 8 + (lane & 7)) * FLH) + ((lane >> 3) & 1) * 8) << 1);
    const uint32_t kvt = kvsm + ((((lane & 15)) * FLH + (lane >> 4) * 8) << 1);
    const int laneRow = (lane >> 4) * 8 + (lane & 7);      // kr B-frag row
    const int khalf   = ((lane >> 3) & 1) * 8;             // kr B-frag k half

    float m0v = -1e30f, m1v = -1e30f, l0v = 0.f, l1v = 0.f;
    float acc_o[8][4];
#pragma unroll
    for (int nt = 0; nt < 8; nt++)
#pragma unroll
        for (int e = 0; e < 4; e++) acc_o[nt][e] = 0.f;

    const int nt0 = 14 - 2 * w;
    float* gw = gsh + w * 16 * FGS;
    const int gi0 = i0 + 16 * w + g;
    const float* mrow0 = mask + ((size_t)b * S_ + gi0) * S_;
    const float* mrow1 = mrow0 + 8 * S_;

    for (int jt = 0; jt < 16; jt++) {
        cp_wait0();
        __syncthreads();
        if (jt < 15) {
            // prefetch kv(jt+1) + 64 new kr ring rows
            const int j1 = (jt + 1) * 64;
            const uint32_t kvb = kvsm + (((jt + 1) & 1) * 64 * FLH << 1);
#pragma unroll
            for (int it = 0; it < 2; it++) {
                const int id = tid + it * 256;
                const int r = id >> 3, c = (id & 7) * 8;
                cpa16(kvb + (r * FLH + c) * 2,
                      &g_kvh[(((size_t)b * S_ + j1 + r) * NH_ + n) * DH_ + c]);
            }
            const int nb = pb0 + 64 * jt + 191;
#pragma unroll
            for (int it = 0; it < 2; it++) {
                const int id = tid + it * 256;
                const int r = id >> 3, c = (id & 7) * 8;
                const int rowabs = nb + r;
                cpa16(krsm + ((rowabs & 255) * FLH + c) * 2,
                      &g_kr[(((size_t)b * POS_ + rowabs) * NH_ + n) * DH_ + c]);
            }
            cp_commit();
        }
        const uint32_t kvo = ((jt & 1) * 64 * FLH) << 1;
        const int j0 = jt * 64;
        const int rowj = pb0 + 64 * jt + laneRow;

        // ---- S = Qw @ KV^T (keep A-fragments for the G pass) ----
        float acc_s[8][4];
#pragma unroll
        for (int nt = 0; nt < 8; nt++)
#pragma unroll
            for (int e = 0; e < 4; e++) acc_s[nt][e] = 0.f;
        uint32_t af[4][4];
#pragma unroll
        for (int kc = 0; kc < 4; kc++) {
            ldsm4(af[kc], qwa + kc * 32);
#pragma unroll
            for (int nn = 0; nn < 4; nn++) {
                uint32_t bf[4];
                ldsm4(bf, kvn + kvo + (((nn * 16) * FLH + kc * 16) << 1));
                mma16816(acc_s[2 * nn + 0], af[kc], &bf[0]);
                mma16816(acc_s[2 * nn + 1], af[kc], &bf[2]);
            }
        }

        // ---- banded G = Qr @ KR_ring^T, scatter pre-shifted ----
        __syncwarp();
#pragma unroll
        for (int np = 0; np < 5; np++) {
            const int tr = (nt0 + 2 * np) * 8;
            const uint32_t kra = krsm + ((((rowj + tr) & 255) * FLH + khalf) << 1);
            float ga[4] = {0.f, 0.f, 0.f, 0.f};
            float gb[4] = {0.f, 0.f, 0.f, 0.f};
#pragma unroll
            for (int kc = 0; kc < 4; kc++) {
                uint32_t bf[4];
                ldsm4(bf, kra + kc * 32);
                uint32_t afr[4] = { hadd2u(af[kc][0], dpk0[kc]),
                                    hadd2u(af[kc][1], dpk0[kc]),
                                    hadd2u(af[kc][2], dpk1[kc]),
                                    hadd2u(af[kc][3], dpk1[kc]) };
                mma16816(ga, afr, &bf[0]);
                mma16816(gb, afr, &bf[2]);
            }
            const int base = tr + 2 * tig + 16 * w - 127;
            const int cA = base + g;
            const int cB = cA + 8;
            if ((unsigned)cA < 64u)        gw[g * FGS + cA]             = ga[0];
            if ((unsigned)(cA + 1) < 64u)  gw[g * FGS + cA + 1]         = ga[1];
            if ((unsigned)cB < 64u)        gw[(g + 8) * FGS + cB]       = ga[2];
            if ((unsigned)(cB + 1) < 64u)  gw[(g + 8) * FGS + cB + 1]   = ga[3];
            const int cA2 = cA + 8;
            const int cB2 = cB + 8;
            if ((unsigned)cA2 < 64u)       gw[g * FGS + cA2]            = gb[0];
            if ((unsigned)(cA2 + 1) < 64u) gw[g * FGS + cA2 + 1]        = gb[1];
            if ((unsigned)cB2 < 64u)       gw[(g + 8) * FGS + cB2]      = gb[2];
            if ((unsigned)(cB2 + 1) < 64u) gw[(g + 8) * FGS + cB2 + 1]  = gb[3];
        }
        __syncwarp();

        // ---- add G, mask, scale; online softmax in registers ----
        float rmax0 = -1e30f, rmax1 = -1e30f;
#pragma unroll
        for (int nt = 0; nt < 8; nt++) {
#pragma unroll
            for (int e = 0; e < 2; e++) {
                const int col = nt * 8 + 2 * tig + e;
                float v0 = (acc_s[nt][e]     + gw[g * FGS + col])       * 0.125f
                           + mrow0[j0 + col] * (-65500.0f);
                float v1 = (acc_s[nt][2 + e] + gw[(g + 8) * FGS + col]) * 0.125f
                           + mrow1[j0 + col] * (-65500.0f);
                acc_s[nt][e] = v0; acc_s[nt][2 + e] = v1;
                rmax0 = fmaxf(rmax0, v0); rmax1 = fmaxf(rmax1, v1);
            }
        }
        rmax0 = fmaxf(rmax0, __shfl_xor_sync(0xffffffffu, rmax0, 1));
        rmax0 = fmaxf(rmax0, __shfl_xor_sync(0xffffffffu, rmax0, 2));
        rmax1 = fmaxf(rmax1, __shfl_xor_sync(0xffffffffu, rmax1, 1));
        rmax1 = fmaxf(rmax1, __shfl_xor_sync(0xffffffffu, rmax1, 2));
        const float mn0 = fmaxf(m0v, rmax0), mn1 = fmaxf(m1v, rmax1);
        const float cr0 = __expf(m0v - mn0), cr1 = __expf(m1v - mn1);
        m0v = mn0; m1v = mn1;
        float ls0 = 0.f, ls1 = 0.f;
#pragma unroll
        for (int nt = 0; nt < 8; nt++) {
#pragma unroll
            for (int e = 0; e < 2; e++) {
                const float p0 = __expf(acc_s[nt][e] - mn0);
                const float p1 = __expf(acc_s[nt][2 + e] - mn1);
                ls0 += p0; ls1 += p1;
                acc_s[nt][e] = p0; acc_s[nt][2 + e] = p1;
            }
        }
        ls0 += __shfl_xor_sync(0xffffffffu, ls0, 1);
        ls0 += __shfl_xor_sync(0xffffffffu, ls0, 2);
        ls1 += __shfl_xor_sync(0xffffffffu, ls1, 1);
        ls1 += __shfl_xor_sync(0xffffffffu, ls1, 2);
        l0v = l0v * cr0 + ls0;
        l1v = l1v * cr1 + ls1;

        // rescale O; pack P fragments (register repack, no smem)
        uint32_t pa[4][4];
#pragma unroll
        for (int kc = 0; kc < 4; kc++) {
            pa[kc][0] = packbf(acc_s[2 * kc][0],     acc_s[2 * kc][1]);
            pa[kc][1] = packbf(acc_s[2 * kc][2],     acc_s[2 * kc][3]);
            pa[kc][2] = packbf(acc_s[2 * kc + 1][0], acc_s[2 * kc + 1][1]);
            pa[kc][3] = packbf(acc_s[2 * kc + 1][2], acc_s[2 * kc + 1][3]);
        }
#pragma unroll
        for (int nt = 0; nt < 8; nt++) {
            acc_o[nt][0] *= cr0; acc_o[nt][1] *= cr0;
            acc_o[nt][2] *= cr1; acc_o[nt][3] *= cr1;
        }

        // ---- O += P @ V ----
#pragma unroll
        for (int kc = 0; kc < 4; kc++) {
#pragma unroll
            for (int nn = 0; nn < 4; nn++) {
                uint32_t bf[4];
                ldsm4t(bf, kvt + kvo + (((kc * 16) * FLH + nn * 16) << 1));
                mma16816(acc_o[2 * nn + 0], pa[kc], &bf[0]);
                mma16816(acc_o[2 * nn + 1], pa[kc], &bf[2]);
            }
        }
    }

    // ---- normalize and store (bf16 ctx) ----
    const float inv0 = 1.f / l0v, inv1 = 1.f / l1v;
    const size_t b0 = (((size_t)b * S_ + i0 + 16 * w + g) * NH_ + n) * (size_t)DH_;
    const size_t b1 = b0 + 8 * (size_t)NH_ * DH_;
#pragma unroll
    for (int nt = 0; nt < 8; nt++) {
        const int c = nt * 8 + 2 * tig;
        *(uint32_t*)&g_ctx[b0 + c] = packbf(acc_o[nt][0] * inv0, acc_o[nt][1] * inv0);
        *(uint32_t*)&g_ctx[b1 + c] = packbf(acc_o[nt][2] * inv1, acc_o[nt][3] * inv1);
    }
}

// -------------------------------- launch ---------------------------------------
extern "C" void kernel_launch(void* const* d_in, const int* in_sizes, int n_in,
                              void* d_out, int out_size)
{
    const float* hidden   = (const float*)d_in[0];
    const float* pos_emb  = (const float*)d_in[1];
    const float* mask     = (const float*)d_in[2];
    const float* qw       = (const float*)d_in[3];
    const float* kvw      = (const float*)d_in[4];
    const float* rw       = (const float*)d_in[5];
    const float* r_r_bias = (const float*)d_in[6];
    const float* r_w_bias = (const float*)d_in[7];
    const float* w_out    = (const float*)d_in[8];
    const float* b_out    = (const float*)d_in[9];
    float* out = (float*)d_out;

    const int gemm_smem  = 3 * PSTG * 2;                        // 107520 B
    const int flash_smem = (128 * FLH + 2 * 64 * FLH + 256 * FLH) * 2
                           + (8 * 16 * FGS + 128) * 4;          // 109056 B
    cudaFuncSetAttribute(proj_all,
                         cudaFuncAttributeMaxDynamicSharedMemorySize, gemm_smem);
    cudaFuncSetAttribute(gemm_epi,
                         cudaFuncAttributeMaxDynamicSharedMemorySize, gemm_smem);
    cudaFuncSetAttribute(flash_mma,
                         cudaFuncAttributeMaxDynamicSharedMemorySize, flash_smem);

    // fp32 -> bf16 conversion of all GEMM inputs
    convert_all<<<2048, 256>>>(hidden, pos_emb, qw, kvw, rw, w_out);

    // q + kv + r projections in a single launch (768 CTAs, 3-stage pipeline)
    proj_all<<<768, 256, gemm_smem>>>();

    // fused attention (kr ring buffer, delta-fragment Qr, banded rel_shift)
    flash_mma<<<dim3(S_/128, NH_, B_), 256, flash_smem>>>(mask, r_w_bias, r_r_bias);

    // output projection + bias + residual + exact GELU
    gemm_epi<<<192, 256, gemm_smem>>>(out, b_out, hidden);
}

// round 7
// speedup vs baseline: 6.6859x; 1.0595x over previous
#include <cuda_runtime.h>
#include <cuda_bf16.h>
#include <math.h>
#include <stdint.h>

#define B_   4
#define S_   1024
#define H_   768
#define NH_  12
#define DH_  64
#define POS_ 2048

// ---------------- scratch (static device arrays; no allocations) ----------------
__device__ __nv_bfloat16 g_hidb[B_*S_*H_];
__device__ __nv_bfloat16 g_posb[B_*POS_*H_];
__device__ __nv_bfloat16 g_qwb [H_*H_];
__device__ __nv_bfloat16 g_kvwb[H_*H_];
__device__ __nv_bfloat16 g_rwgt[H_*H_];
__device__ __nv_bfloat16 g_wob [H_*H_];
__device__ __nv_bfloat16 g_maskb[B_*S_*S_];   // mask * -65500, bf16
__device__ __nv_bfloat16 g_qh [B_*S_*H_];
__device__ __nv_bfloat16 g_kvh[B_*S_*H_];
__device__ __nv_bfloat16 g_kr [B_*POS_*H_];
__device__ __nv_bfloat16 g_ctx[B_*S_*H_];

// ---------------- PTX helpers ---------------------------------------------------
__device__ __forceinline__ uint32_t sptr(const void* p) {
    return (uint32_t)__cvta_generic_to_shared(p);
}
__device__ __forceinline__ void ldsm4(uint32_t* r, uint32_t a) {
    asm volatile("ldmatrix.sync.aligned.m8n8.x4.shared.b16 {%0,%1,%2,%3},[%4];"
                 : "=r"(r[0]), "=r"(r[1]), "=r"(r[2]), "=r"(r[3]) : "r"(a));
}
__device__ __forceinline__ void ldsm4t(uint32_t* r, uint32_t a) {
    asm volatile("ldmatrix.sync.aligned.m8n8.x4.trans.shared.b16 {%0,%1,%2,%3},[%4];"
                 : "=r"(r[0]), "=r"(r[1]), "=r"(r[2]), "=r"(r[3]) : "r"(a));
}
__device__ __forceinline__ void mma16816(float* d, const uint32_t* a, const uint32_t* b) {
    asm volatile(
        "mma.sync.aligned.m16n8k16.row.col.f32.bf16.bf16.f32 "
        "{%0,%1,%2,%3},{%4,%5,%6,%7},{%8,%9},{%0,%1,%2,%3};"
        : "+f"(d[0]), "+f"(d[1]), "+f"(d[2]), "+f"(d[3])
        : "r"(a[0]), "r"(a[1]), "r"(a[2]), "r"(a[3]), "r"(b[0]), "r"(b[1]));
}
__device__ __forceinline__ void cpa16(uint32_t dst, const void* src) {
    asm volatile("cp.async.cg.shared.global [%0], [%1], 16;" :: "r"(dst), "l"(src));
}
__device__ __forceinline__ void cp_commit() {
    asm volatile("cp.async.commit_group;");
}
__device__ __forceinline__ void cp_wait0() {
    asm volatile("cp.async.wait_group 0;");
}
__device__ __forceinline__ void cp_wait1() {
    asm volatile("cp.async.wait_group 1;");
}
__device__ __forceinline__ uint32_t packbf(float a, float b) {
    __nv_bfloat162 h = __float22bfloat162_rn(make_float2(a, b));
    return *(uint32_t*)&h;
}
__device__ __forceinline__ uint32_t hadd2u(uint32_t a, uint32_t b) {
    __nv_bfloat162 r = __hadd2(*(__nv_bfloat162*)&a, *(__nv_bfloat162*)&b);
    return *(uint32_t*)&r;
}

// ---------------- fp32 -> bf16 conversion (all tensors + mask) ------------------
__global__ void convert_all(const float* __restrict__ h, const float* __restrict__ p,
                            const float* __restrict__ qw, const float* __restrict__ kvw,
                            const float* __restrict__ rw, const float* __restrict__ wo,
                            const float* __restrict__ mk)
{
    const int N1 = 786432;            // hidden  (float4 units)
    const int N2 = N1 + 1572864;      // pos_emb
    const int N3 = N2 + 147456;       // qw
    const int N4 = N3 + 147456;       // kvw
    const int N5 = N4 + 147456;       // rw
    const int N6 = N5 + 147456;       // wo
    const int N7 = N6 + 1048576;      // mask (premultiplied)
    for (int i = blockIdx.x * blockDim.x + threadIdx.x; i < N7;
         i += gridDim.x * blockDim.x) {
        const float* src; __nv_bfloat16* dst; int li; float sc = 1.f;
        if      (i < N1) { src = h;   dst = g_hidb; li = i; }
        else if (i < N2) { src = p;   dst = g_posb; li = i - N1; }
        else if (i < N3) { src = qw;  dst = g_qwb;  li = i - N2; }
        else if (i < N4) { src = kvw; dst = g_kvwb; li = i - N3; }
        else if (i < N5) { src = rw;  dst = g_rwgt; li = i - N4; }
        else if (i < N6) { src = wo;  dst = g_wob;  li = i - N5; }
        else             { src = mk;  dst = g_maskb; li = i - N6; sc = -65500.f; }
        float4 v = ((const float4*)src)[li];
        uint2 u;
        u.x = packbf(v.x * sc, v.y * sc);
        u.y = packbf(v.z * sc, v.w * sc);
        ((uint2*)dst)[li] = u;
    }
}

// ---------------- 3-stage bf16 GEMM core, 128x128x64 tiles, K=N=768 -------------
#define PSTG 17920      // halves per stage
#define NKI  12         // 768 / 64

__device__ __forceinline__ void pj_load(int tid, const __nv_bfloat16* A,
    const __nv_bfloat16* W, int m0, int c0, int k0, uint32_t sbase)
{
#pragma unroll
    for (int it = 0; it < 4; it++) {
        const int id = tid + it * 256;
        const int r = id >> 3, c = (id & 7) * 8;
        cpa16(sbase + (r * 72 + c) * 2, &A[(size_t)(m0 + r) * H_ + k0 + c]);
    }
#pragma unroll
    for (int it = 0; it < 4; it++) {
        const int id = tid + it * 256;
        const int r = id >> 4, c = (id & 15) * 8;
        cpa16(sbase + (9216 + r * 136 + c) * 2, &W[(size_t)(k0 + r) * H_ + c0 + c]);
    }
    cp_commit();
}

template<bool EPI>
__device__ __forceinline__ void gemm3_body(
    const __nv_bfloat16* __restrict__ A, const __nv_bfloat16* __restrict__ W,
    int m0, int c0, __nv_bfloat16* __restrict__ outH, float* __restrict__ outF,
    const float* __restrict__ bias, const float* __restrict__ resid)
{
    extern __shared__ __align__(16) __nv_bfloat16 gsm[];
    const int tid = threadIdx.x;
    const int wid = tid >> 5, lane = tid & 31;
    const int wm = wid & 1, wn = wid >> 1;
    const int g = lane >> 2, tig = lane & 3;

    const uint32_t s0 = sptr(gsm);
    pj_load(tid, A, W, m0, c0, 0,  s0);
    pj_load(tid, A, W, m0, c0, 64, s0 + (PSTG << 1));

    float acc[4][4][4];
#pragma unroll
    for (int mi = 0; mi < 4; mi++)
#pragma unroll
        for (int nt = 0; nt < 4; nt++)
#pragma unroll
            for (int e = 0; e < 4; e++) acc[mi][nt][e] = 0.f;

    const uint32_t a_off = ((wm * 64 + (lane & 15)) * 72 + (lane >> 4) * 8) << 1;
    const uint32_t b_off = (9216 + ((lane & 15)) * 136 + wn * 32 + (lane >> 4) * 8) << 1;

    for (int ki = 0; ki < NKI; ki++) {
        if (ki == NKI - 1) cp_wait0(); else cp_wait1();
        __syncthreads();
        if (ki + 2 < NKI)
            pj_load(tid, A, W, m0, c0, (ki + 2) * 64,
                    s0 + (((ki + 2) % 3) * PSTG << 1));
        const uint32_t sb = s0 + ((ki % 3) * PSTG << 1);
        const uint32_t a_base = sb + a_off, b_base = sb + b_off;

        // fragment double-buffer over kc
        uint32_t af[2][4][4], bv[2][2][4];
#pragma unroll
        for (int mi = 0; mi < 4; mi++)
            ldsm4(af[0][mi], a_base + ((mi * 16 * 72) << 1));
#pragma unroll
        for (int nn = 0; nn < 2; nn++)
            ldsm4t(bv[0][nn], b_base + ((nn * 16) << 1));
#pragma unroll
        for (int kc = 0; kc < 4; kc++) {
            const int cur = kc & 1;
            if (kc < 3) {
                const int nx = cur ^ 1, kn = kc + 1;
#pragma unroll
                for (int mi = 0; mi < 4; mi++)
                    ldsm4(af[nx][mi], a_base + ((mi * 16 * 72 + kn * 16) << 1));
#pragma unroll
                for (int nn = 0; nn < 2; nn++)
                    ldsm4t(bv[nx][nn], b_base + ((kn * 16 * 136 + nn * 16) << 1));
            }
#pragma unroll
            for (int mi = 0; mi < 4; mi++)
#pragma unroll
                for (int nn = 0; nn < 2; nn++) {
                    mma16816(acc[mi][2 * nn + 0], af[cur][mi], &bv[cur][nn][0]);
                    mma16816(acc[mi][2 * nn + 1], af[cur][mi], &bv[cur][nn][2]);
                }
        }
    }

#pragma unroll
    for (int mi = 0; mi < 4; mi++) {
#pragma unroll
        for (int nt = 0; nt < 4; nt++) {
            const int col = c0 + wn * 32 + nt * 8 + 2 * tig;
#pragma unroll
            for (int half = 0; half < 2; half++) {
                const int r = m0 + wm * 64 + mi * 16 + g + half * 8;
                float v0 = acc[mi][nt][half * 2 + 0];
                float v1 = acc[mi][nt][half * 2 + 1];
                if (EPI) {
                    float x0 = v0 + bias[col]     + resid[(size_t)r * H_ + col];
                    float x1 = v1 + bias[col + 1] + resid[(size_t)r * H_ + col + 1];
                    v0 = 0.5f * x0 * (1.f + erff(x0 * 0.70710678118654752f));
                    v1 = 0.5f * x1 * (1.f + erff(x1 * 0.70710678118654752f));
                    float* cp = &outF[(size_t)r * H_ + col];
                    cp[0] = v0; cp[1] = v1;
                } else {
                    *(uint32_t*)&outH[(size_t)r * H_ + col] = packbf(v0, v1);
                }
            }
        }
    }
}

// All three projections in ONE launch: 768 blocks.
__global__ __launch_bounds__(256, 2) void proj_all()
{
    const int bid = blockIdx.x;
    const __nv_bfloat16 *A, *W;
    __nv_bfloat16* C;
    int m0, c0;
    if (bid < 384) {
        const int x = bid % 12, y = bid / 12;
        m0 = y * 128;
        A = g_hidb;
        if (x < 6) { W = g_qwb;  C = g_qh;  c0 = x * 128; }
        else       { W = g_kvwb; C = g_kvh; c0 = (x - 6) * 128; }
    } else {
        const int t = bid - 384;
        const int x = t % 6, y = t / 6;
        m0 = y * 128; c0 = x * 128;
        A = g_posb; W = g_rwgt; C = g_kr;
    }
    gemm3_body<false>(A, W, m0, c0, C, nullptr, nullptr, nullptr);
}

// Output projection + bias + residual + exact GELU. 192 blocks.
__global__ __launch_bounds__(256, 2) void gemm_epi(
    float* __restrict__ out, const float* __restrict__ bias,
    const float* __restrict__ resid)
{
    const int x = blockIdx.x % 6, y = blockIdx.x / 6;
    gemm3_body<true>(g_ctx, g_wob, y * 128, x * 128, nullptr, out, bias, resid);
}

// ---------------- FA2-style flash attention, hoisted fragments ------------------
#define FLH 72
#define FGS 68
__global__ __launch_bounds__(256, 2) void flash_mma(
    const float* __restrict__ rwbias, const float* __restrict__ rrbias)
{
    extern __shared__ __align__(16) char smraw[];
    __nv_bfloat16* qw_s = (__nv_bfloat16*)smraw;        // 128 x 72
    __nv_bfloat16* kv_s = qw_s + 128 * FLH;             // 2 x 64 x 72
    __nv_bfloat16* kr_s = kv_s + 2 * 64 * FLH;          // ring: 256 x 72
    float* gsh = (float*)(kr_s + 256 * FLH);            // 8 x 16 x 68
    float* bw  = gsh + 8 * 16 * FGS;                    // 64
    float* br  = bw + 64;                               // 64

    const int b = blockIdx.z, n = blockIdx.y;
    const int i0 = blockIdx.x * 128;
    const int tid = threadIdx.x;
    const int w = tid >> 5, lane = tid & 31;
    const int g = lane >> 2, tig = lane & 3;
    const int pb0 = 897 - i0;   // absolute kr row of window start at jt=0

    if (tid < 64)       bw[tid]      = rwbias[n * DH_ + tid];
    else if (tid < 128) br[tid - 64] = rrbias[n * DH_ + tid - 64];
    __syncthreads();

    const uint32_t kvsm = sptr(kv_s), krsm = sptr(kr_s);

    // ---- initial async loads: kv tile 0 + full 191-row kr window ----
#pragma unroll
    for (int it = 0; it < 2; it++) {
        const int id = tid + it * 256;
        const int r = id >> 3, c = (id & 7) * 8;
        cpa16(kvsm + (r * FLH + c) * 2,
              &g_kvh[(((size_t)b * S_ + r) * NH_ + n) * DH_ + c]);
    }
#pragma unroll
    for (int it = 0; it < 6; it++) {
        const int id = tid + it * 256;
        const int r = id >> 3, c = (id & 7) * 8;
        if (r < 191) {
            const int rowabs = pb0 + r;
            cpa16(krsm + ((rowabs & 255) * FLH + c) * 2,
                  &g_kr[(((size_t)b * POS_ + rowabs) * NH_ + n) * DH_ + c]);
        }
    }
    cp_commit();

    // ---- build biased+scaled Q tile: (q + r_w_bias) * 0.125 ----
#pragma unroll
    for (int it = 0; it < 4; it++) {
        const int id = tid + it * 256;
        const int r = id >> 3, c = (id & 7) * 8;
        uint4 v = *(const uint4*)&g_qh[(((size_t)b * S_ + i0 + r) * NH_ + n) * DH_ + c];
        __nv_bfloat162* hp = (__nv_bfloat162*)&v;
        uint4 ow;
        uint32_t* wp = (uint32_t*)&ow;
#pragma unroll
        for (int k = 0; k < 4; k++) {
            float2 f = __bfloat1622float2(hp[k]);
            wp[k] = packbf((f.x + bw[c + 2 * k]) * 0.125f,
                           (f.y + bw[c + 2 * k + 1]) * 0.125f);
        }
        *(uint4*)&qw_s[r * FLH + c] = ow;
    }

    // ---- delta fragments: packed bf16 (br - bw)*0.125 ----
    uint32_t dpk0[4], dpk1[4];
#pragma unroll
    for (int kc = 0; kc < 4; kc++) {
        const int kA = 16 * kc + 2 * tig;
        dpk0[kc] = packbf((br[kA] - bw[kA]) * 0.125f, (br[kA + 1] - bw[kA + 1]) * 0.125f);
        dpk1[kc] = packbf((br[kA + 8] - bw[kA + 8]) * 0.125f, (br[kA + 9] - bw[kA + 9]) * 0.125f);
    }
    __syncthreads();

    // ---- hoist Q fragments (jt-invariant) and delta-added Qr fragments ----
    const uint32_t qwa = sptr(qw_s) + (((16 * w + (lane & 15)) * FLH + (lane >> 4) * 8) << 1);
    uint32_t af[4][4], afr[4][4];
#pragma unroll
    for (int kc = 0; kc < 4; kc++) {
        ldsm4(af[kc], qwa + kc * 32);
        afr[kc][0] = hadd2u(af[kc][0], dpk0[kc]);
        afr[kc][1] = hadd2u(af[kc][1], dpk0[kc]);
        afr[kc][2] = hadd2u(af[kc][2], dpk1[kc]);
        afr[kc][3] = hadd2u(af[kc][3], dpk1[kc]);
    }

    const uint32_t kvn = kvsm + (((((lane >> 4) * 8 + (lane & 7)) * FLH) + ((lane >> 3) & 1) * 8) << 1);
    const uint32_t kvt = kvsm + ((((lane & 15)) * FLH + (lane >> 4) * 8) << 1);
    const int laneRow = (lane >> 4) * 8 + (lane & 7);
    const int khalf   = ((lane >> 3) & 1) * 8;

    float m0v = -1e30f, m1v = -1e30f, l0v = 0.f, l1v = 0.f;
    float acc_o[8][4];
#pragma unroll
    for (int nt = 0; nt < 8; nt++)
#pragma unroll
        for (int e = 0; e < 4; e++) acc_o[nt][e] = 0.f;

    const int nt0 = 14 - 2 * w;
    float* gw = gsh + w * 16 * FGS;
    const int gi0 = i0 + 16 * w + g;
    const __nv_bfloat16* mrow0 = g_maskb + ((size_t)b * S_ + gi0) * S_;
    const __nv_bfloat16* mrow1 = mrow0 + 8 * S_;

    for (int jt = 0; jt < 16; jt++) {
        cp_wait0();
        __syncthreads();
        if (jt < 15) {
            const int j1 = (jt + 1) * 64;
            const uint32_t kvb = kvsm + (((jt + 1) & 1) * 64 * FLH << 1);
#pragma unroll
            for (int it = 0; it < 2; it++) {
                const int id = tid + it * 256;
                const int r = id >> 3, c = (id & 7) * 8;
                cpa16(kvb + (r * FLH + c) * 2,
                      &g_kvh[(((size_t)b * S_ + j1 + r) * NH_ + n) * DH_ + c]);
            }
            const int nb = pb0 + 64 * jt + 191;
#pragma unroll
            for (int it = 0; it < 2; it++) {
                const int id = tid + it * 256;
                const int r = id >> 3, c = (id & 7) * 8;
                const int rowabs = nb + r;
                cpa16(krsm + ((rowabs & 255) * FLH + c) * 2,
                      &g_kr[(((size_t)b * POS_ + rowabs) * NH_ + n) * DH_ + c]);
            }
            cp_commit();
        }
        const uint32_t kvo = ((jt & 1) * 64 * FLH) << 1;
        const int j0 = jt * 64;
        const int rowj = pb0 + 64 * jt + laneRow;

        // ---- S = Qw @ KV^T, pipelined B fragments ----
        float acc_s[8][4];
#pragma unroll
        for (int nt = 0; nt < 8; nt++)
#pragma unroll
            for (int e = 0; e < 4; e++) acc_s[nt][e] = 0.f;
        {
            uint32_t sbf[2][4];
            ldsm4(sbf[0], kvn + kvo);
#pragma unroll
            for (int kc = 0; kc < 4; kc++) {
#pragma unroll
                for (int nn = 0; nn < 4; nn++) {
                    const int it = kc * 4 + nn;
                    const int cur = it & 1;
                    if (it < 15) {
                        const int itn = it + 1;
                        const int kn = itn >> 2, nnn = itn & 3;
                        ldsm4(sbf[cur ^ 1], kvn + kvo + ((nnn * 16 * FLH + kn * 16) << 1));
                    }
                    mma16816(acc_s[2 * nn + 0], af[kc], &sbf[cur][0]);
                    mma16816(acc_s[2 * nn + 1], af[kc], &sbf[cur][2]);
                }
            }
        }

        // ---- banded G = Qr @ KR_ring^T, pipelined, scatter pre-shifted ----
        __syncwarp();
        {
            uint32_t gbf[2][4];
            {
                const int tr0 = nt0 * 8;
                ldsm4(gbf[0], krsm + ((((rowj + tr0) & 255) * FLH + khalf) << 1));
            }
#pragma unroll
            for (int np = 0; np < 5; np++) {
                const int tr = (nt0 + 2 * np) * 8;
                float ga[4] = {0.f, 0.f, 0.f, 0.f};
                float gb[4] = {0.f, 0.f, 0.f, 0.f};
#pragma unroll
                for (int kc = 0; kc < 4; kc++) {
                    const int it = np * 4 + kc;
                    const int cur = it & 1;
                    if (it < 19) {
                        const int itn = it + 1;
                        const int npn = itn >> 2, kn = itn & 3;
                        const int trn = (nt0 + 2 * npn) * 8;
                        ldsm4(gbf[cur ^ 1],
                              krsm + ((((rowj + trn) & 255) * FLH + khalf) << 1) + kn * 32);
                    }
                    mma16816(ga, afr[kc], &gbf[cur][0]);
                    mma16816(gb, afr[kc], &gbf[cur][2]);
                }
                const int base = tr + 2 * tig + 16 * w - 127;
                const int cA = base + g;
                const int cB = cA + 8;
                if ((unsigned)cA < 64u)        gw[g * FGS + cA]             = ga[0];
                if ((unsigned)(cA + 1) < 64u)  gw[g * FGS + cA + 1]         = ga[1];
                if ((unsigned)cB < 64u)        gw[(g + 8) * FGS + cB]       = ga[2];
                if ((unsigned)(cB + 1) < 64u)  gw[(g + 8) * FGS + cB + 1]   = ga[3];
                const int cA2 = cA + 8;
                const int cB2 = cB + 8;
                if ((unsigned)cA2 < 64u)       gw[g * FGS + cA2]            = gb[0];
                if ((unsigned)(cA2 + 1) < 64u) gw[g * FGS + cA2 + 1]        = gb[1];
                if ((unsigned)cB2 < 64u)       gw[(g + 8) * FGS + cB2]      = gb[2];
                if ((unsigned)(cB2 + 1) < 64u) gw[(g + 8) * FGS + cB2 + 1]  = gb[3];
            }
        }
        __syncwarp();

        // ---- add G + bf16 mask; online softmax (scores pre-scaled) ----
        float rmax0 = -1e30f, rmax1 = -1e30f;
#pragma unroll
        for (int nt = 0; nt < 8; nt++) {
            const int colb = nt * 8 + 2 * tig;
            const float2 mv0 = __bfloat1622float2(
                *(const __nv_bfloat162*)&mrow0[j0 + colb]);
            const float2 mv1 = __bfloat1622float2(
                *(const __nv_bfloat162*)&mrow1[j0 + colb]);
            float v;
            v = acc_s[nt][0] + gw[g * FGS + colb]           + mv0.x;
            acc_s[nt][0] = v; rmax0 = fmaxf(rmax0, v);
            v = acc_s[nt][1] + gw[g * FGS + colb + 1]       + mv0.y;
            acc_s[nt][1] = v; rmax0 = fmaxf(rmax0, v);
            v = acc_s[nt][2] + gw[(g + 8) * FGS + colb]     + mv1.x;
            acc_s[nt][2] = v; rmax1 = fmaxf(rmax1, v);
            v = acc_s[nt][3] + gw[(g + 8) * FGS + colb + 1] + mv1.y;
            acc_s[nt][3] = v; rmax1 = fmaxf(rmax1, v);
        }
        rmax0 = fmaxf(rmax0, __shfl_xor_sync(0xffffffffu, rmax0, 1));
        rmax0 = fmaxf(rmax0, __shfl_xor_sync(0xffffffffu, rmax0, 2));
        rmax1 = fmaxf(rmax1, __shfl_xor_sync(0xffffffffu, rmax1, 1));
        rmax1 = fmaxf(rmax1, __shfl_xor_sync(0xffffffffu, rmax1, 2));
        const float mn0 = fmaxf(m0v, rmax0), mn1 = fmaxf(m1v, rmax1);
        const float cr0 = __expf(m0v - mn0), cr1 = __expf(m1v - mn1);
        m0v = mn0; m1v = mn1;
        float ls0 = 0.f, ls1 = 0.f;
#pragma unroll
        for (int nt = 0; nt < 8; nt++) {
#pragma unroll
            for (int e = 0; e < 2; e++) {
                const float p0 = __expf(acc_s[nt][e] - mn0);
                const float p1 = __expf(acc_s[nt][2 + e] - mn1);
                ls0 += p0; ls1 += p1;
                acc_s[nt][e] = p0; acc_s[nt][2 + e] = p1;
            }
        }
        ls0 += __shfl_xor_sync(0xffffffffu, ls0, 1);
        ls0 += __shfl_xor_sync(0xffffffffu, ls0, 2);
        ls1 += __shfl_xor_sync(0xffffffffu, ls1, 1);
        ls1 += __shfl_xor_sync(0xffffffffu, ls1, 2);
        l0v = l0v * cr0 + ls0;
        l1v = l1v * cr1 + ls1;

        // rescale O; pack P fragments
        uint32_t pa[4][4];
#pragma unroll
        for (int kc = 0; kc < 4; kc++) {
            pa[kc][0] = packbf(acc_s[2 * kc][0],     acc_s[2 * kc][1]);
            pa[kc][1] = packbf(acc_s[2 * kc][2],     acc_s[2 * kc][3]);
            pa[kc][2] = packbf(acc_s[2 * kc + 1][0], acc_s[2 * kc + 1][1]);
            pa[kc][3] = packbf(acc_s[2 * kc + 1][2], acc_s[2 * kc + 1][3]);
        }
#pragma unroll
        for (int nt = 0; nt < 8; nt++) {
            acc_o[nt][0] *= cr0; acc_o[nt][1] *= cr0;
            acc_o[nt][2] *= cr1; acc_o[nt][3] *= cr1;
        }

        // ---- O += P @ V, pipelined B fragments ----
        {
            uint32_t obf[2][4];
            ldsm4t(obf[0], kvt + kvo);
#pragma unroll
            for (int kc = 0; kc < 4; kc++) {
#pragma unroll
                for (int nn = 0; nn < 4; nn++) {
                    const int it = kc * 4 + nn;
                    const int cur = it & 1;
                    if (it < 15) {
                        const int itn = it + 1;
                        const int kn = itn >> 2, nnn = itn & 3;
                        ldsm4t(obf[cur ^ 1], kvt + kvo + ((kn * 16 * FLH + nnn * 16) << 1));
                    }
                    mma16816(acc_o[2 * nn + 0], pa[kc], &obf[cur][0]);
                    mma16816(acc_o[2 * nn + 1], pa[kc], &obf[cur][2]);
                }
            }
        }
    }

    // ---- normalize and store (bf16 ctx) ----
    const float inv0 = 1.f / l0v, inv1 = 1.f / l1v;
    const size_t b0 = (((size_t)b * S_ + i0 + 16 * w + g) * NH_ + n) * (size_t)DH_;
    const size_t b1 = b0 + 8 * (size_t)NH_ * DH_;
#pragma unroll
    for (int nt = 0; nt < 8; nt++) {
        const int c = nt * 8 + 2 * tig;
        *(uint32_t*)&g_ctx[b0 + c] = packbf(acc_o[nt][0] * inv0, acc_o[nt][1] * inv0);
        *(uint32_t*)&g_ctx[b1 + c] = packbf(acc_o[nt][2] * inv1, acc_o[nt][3] * inv1);
    }
}

// -------------------------------- launch ---------------------------------------
extern "C" void kernel_launch(void* const* d_in, const int* in_sizes, int n_in,
                              void* d_out, int out_size)
{
    const float* hidden   = (const float*)d_in[0];
    const float* pos_emb  = (const float*)d_in[1];
    const float* mask     = (const float*)d_in[2];
    const float* qw       = (const float*)d_in[3];
    const float* kvw      = (const float*)d_in[4];
    const float* rw       = (const float*)d_in[5];
    const float* r_r_bias = (const float*)d_in[6];
    const float* r_w_bias = (const float*)d_in[7];
    const float* w_out    = (const float*)d_in[8];
    const float* b_out    = (const float*)d_in[9];
    float* out = (float*)d_out;

    const int gemm_smem  = 3 * PSTG * 2;                        // 107520 B
    const int flash_smem = (128 * FLH + 2 * 64 * FLH + 256 * FLH) * 2
                           + (8 * 16 * FGS + 128) * 4;          // 109056 B
    cudaFuncSetAttribute(proj_all,
                         cudaFuncAttributeMaxDynamicSharedMemorySize, gemm_smem);
    cudaFuncSetAttribute(gemm_epi,
                         cudaFuncAttributeMaxDynamicSharedMemorySize, gemm_smem);
    cudaFuncSetAttribute(flash_mma,
                         cudaFuncAttributeMaxDynamicSharedMemorySize, flash_smem);

    // fp32 -> bf16 conversion (inputs, weights, premultiplied mask)
    convert_all<<<2048, 256>>>(hidden, pos_emb, qw, kvw, rw, w_out, mask);

    // q + kv + r projections in a single launch
    proj_all<<<768, 256, gemm_smem>>>();

    // fused attention
    flash_mma<<<dim3(S_/128, NH_, B_), 256, flash_smem>>>(r_w_bias, r_r_bias);

    // output projection + bias + residual + exact GELU
    gemm_epi<<<192, 256, gemm_smem>>>(out, b_out, hidden);
}